// round 5
// baseline (speedup 1.0000x reference)
#include <cuda_runtime.h>
#include <cuda_bf16.h>
#include <cstdint>

#define HH 150
#define APITCH 152          // g_A/g_B row pitch (floats)

#define EPITCH 392          // E row pitch in u32 words
#define H1PITCH 88          // h1 row pitch in u32 words
#define WABPITCH 36         // k1 weight row pitch (u32 words)

// Packed-fragment W blob geometry: per k16-step: 32 lanes * 44 words
#define PKS 1408
#define W1C_CHUNK_W 11264   // 8 ks (K=128 chunk)
#define W2_W 14080          // 10 ks (K=160)
#define W2_SLAB_W 7040      // 5 ks

// ---------------- device scratch ----------------
__device__ __align__(16) uint32_t      g_Ebf[1536 * EPITCH];
__device__ __align__(16) __nv_bfloat16 g_wabT[12 * 320 * 72];
__device__ __align__(16) uint32_t      g_w1cP[6 * W1C_CHUNK_W];
__device__ __align__(16) uint32_t      g_w2P[W2_W];
__device__ __align__(16) float g_A[1536 * APITCH];
__device__ __align__(16) float g_B[1536 * APITCH];
__device__ float g_S[8 * 192 * 192];

// ---------------- helpers ----------------
__device__ __forceinline__ uint32_t smem_u32(const void* p) {
    uint32_t a;
    asm("{ .reg .u64 t; cvta.to.shared.u64 t, %1; cvt.u32.u64 %0, t; }" : "=r"(a) : "l"(p));
    return a;
}
__device__ __forceinline__ uint32_t packbf(float lo, float hi) {
    uint32_t d; asm("cvt.rn.bf16x2.f32 %0, %1, %2;" : "=r"(d) : "f"(hi), "f"(lo)); return d;
}
__device__ __forceinline__ uint32_t bmul2(uint32_t a, uint32_t b) {
    uint32_t d; asm("mul.rn.bf16x2 %0, %1, %2;" : "=r"(d) : "r"(a), "r"(b)); return d;
}
__device__ __forceinline__ void mma16816(float* d, const uint32_t* a, const uint32_t* b,
                                         const float* c) {
    asm volatile(
        "mma.sync.aligned.m16n8k16.row.col.f32.bf16.bf16.f32 "
        "{%0,%1,%2,%3}, {%4,%5,%6,%7}, {%8,%9}, {%10,%11,%12,%13};"
        : "=f"(d[0]), "=f"(d[1]), "=f"(d[2]), "=f"(d[3])
        : "r"(a[0]), "r"(a[1]), "r"(a[2]), "r"(a[3]), "r"(b[0]), "r"(b[1]),
          "f"(c[0]), "f"(c[1]), "f"(c[2]), "f"(c[3]));
}
#define MBAR_INIT(mb, cnt) asm volatile("mbarrier.init.shared.b64 [%0], %1;" :: "r"((uint32_t)(mb)), "r"((uint32_t)(cnt)) : "memory")
#define MBAR_EXPECT_TX(mb, n) asm volatile("mbarrier.arrive.expect_tx.shared.b64 _, [%0], %1;" :: "r"((uint32_t)(mb)), "r"((uint32_t)(n)) : "memory")
#define FENCE_ASYNC() asm volatile("fence.proxy.async.shared::cta;" ::: "memory")
#define NBAR(id, cnt) asm volatile("bar.sync %0, %1;" :: "r"(id), "r"(cnt) : "memory")
#define MBAR_WAIT(mb, ph) do { \
    uint32_t _m = (uint32_t)(mb); uint32_t _p = (uint32_t)(ph); uint32_t _d; \
    asm volatile("{\n\t.reg .pred p;\n\tmbarrier.try_wait.parity.acquire.cta.shared::cta.b64 p, [%1], %2;\n\tselp.b32 %0, 1, 0, p;\n\t}" \
        : "=r"(_d) : "r"(_m), "r"(_p) : "memory"); \
    if (!_d) { \
        asm volatile("{\n\t.reg .pred P1;\n\tWL_%=:\n\tmbarrier.try_wait.parity.acquire.cta.shared::cta.b64 P1, [%0], %1, 0x989680;\n\t@P1 bra.uni WD_%=;\n\tbra.uni WL_%=;\n\tWD_%=:\n\t}" \
            :: "r"(_m), "r"(_p) : "memory"); \
    } } while (0)
__device__ __forceinline__ void bulk_g2s(uint32_t dst, const void* src, uint32_t bytes, uint32_t mbar) {
    asm volatile("cp.async.bulk.shared::cta.global.mbarrier::complete_tx::bytes [%0], [%1], %2, [%3];"
        :: "r"(dst), "l"(src), "r"(bytes), "r"(mbar) : "memory");
}

// ---------------- prep: E -> interleaved bf16x2 ----------------
__global__ void kprep_e(const float* __restrict__ E) {
    int idx = blockIdx.x * 256 + threadIdx.x;
    if (idx >= 1536 * EPITCH) return;
    int r = idx / EPITCH, pos = idx % EPITCH;
    int g = pos >> 3, wi = pos & 7, q = wi >> 1, h = wi & 1;
    int kw = g * 8 + q + 4 * h;
    uint32_t v = 0;
    if (kw < 384) {
        float2 e = *reinterpret_cast<const float2*>(E + (size_t)r * 768 + 2 * kw);
        v = packbf(e.x, e.y);
    }
    g_Ebf[idx] = v;
}

// ---------------- prep: weights ----------------
#define WAB_N (12 * 320 * 72)
#define W1CP_N (6 * W1C_CHUNK_W)
__global__ void kprep_w(const float* __restrict__ W1, const float* __restrict__ W2) {
    int idx = blockIdx.x * 256 + threadIdx.x;
    if (idx < WAB_N) {
        int c = idx / (320 * 72), rem = idx % (320 * 72);
        int n = rem / 72, kk = rem % 72;
        float v = 0.f;
        if (kk < 64) {
            int kg = c * 64 + kk;
            if (n < 160) { if (n < HH) v = W1[(size_t)kg * HH + n]; }
            else { int h = n - 160; if (h < HH) v = W1[(size_t)(768 + kg) * HH + h]; }
        }
        g_wabT[idx] = __float2bfloat16(v);
    } else if (idx < WAB_N + W1CP_N + W2_W) {
        int t = idx - WAB_N;
        bool isW2 = (t >= W1CP_N);
        int c = 0, r;
        if (isW2) r = t - W1CP_N;
        else { c = t / W1C_CHUNK_W; r = t % W1C_CHUNK_W; }
        int ks = r / PKS, r1 = r % PKS;
        int lane = r1 / 44, r2 = r1 % 44;
        uint32_t v = 0;
        if (r2 < 40) {
            int nh = r2 / 20, r3 = r2 % 20, m = r3 / 4, e = r3 % 4;
            int gq = lane >> 2, qq = lane & 3;
            int nb = nh * 10 + 2 * m + (e >> 1);
            int kwl = ks * 8 + qq + (e & 1) * 4;
            int n = nb * 8 + gq;
            float v0 = 0.f, v1 = 0.f;
            if (n < HH) {
                if (isW2) {
                    int k0 = 2 * kwl;
                    if (k0 < HH)     v0 = W2[(size_t)k0 * HH + n];
                    if (k0 + 1 < HH) v1 = W2[(size_t)(k0 + 1) * HH + n];
                } else {
                    int k0 = c * 128 + 2 * kwl;
                    v0 = W1[(size_t)(1536 + k0) * HH + n];
                    v1 = W1[(size_t)(1536 + k0 + 1) * HH + n];
                }
            }
            v = packbf(v0, v1);
        }
        if (isW2) g_w2P[r] = v; else g_w1cP[(size_t)c * W1C_CHUNK_W + r] = v;
    }
}

// ---------------- k1: seeds GEMM -> g_A,g_B (pitch 152) ----------------
#define K1_E_BYTES (32 * EPITCH * 4)
#define K1_W_BYTES (320 * WABPITCH * 4)
#define K1_BAR_OFF (K1_E_BYTES + 2 * K1_W_BYTES)
#define K1_SMEM    (K1_BAR_OFF + 64)

__global__ __launch_bounds__(256, 1)
void k1_mma(const float* __restrict__ b1) {
    extern __shared__ __align__(128) char smem[];
    uint32_t* sE = (uint32_t*)smem;
    uint32_t* sW[2] = { (uint32_t*)(smem + K1_E_BYTES),
                        (uint32_t*)(smem + K1_E_BYTES + K1_W_BYTES) };
    const uint32_t barE = smem_u32(smem + K1_BAR_OFF);
    const uint32_t barW[2] = { barE + 8, barE + 16 };
    const int tid = threadIdx.x, w = tid >> 5, lane = tid & 31;
    const int gq = lane >> 2, qq = lane & 3;
    const int r0 = blockIdx.x * 32;

    if (tid == 0) {
        MBAR_INIT(barE, 1); MBAR_INIT(barW[0], 1); MBAR_INIT(barW[1], 1);
        FENCE_ASYNC();
        MBAR_EXPECT_TX(barE, K1_E_BYTES);
        bulk_g2s(smem_u32(sE), g_Ebf + (size_t)r0 * EPITCH, K1_E_BYTES, barE);
        MBAR_EXPECT_TX(barW[0], K1_W_BYTES);
        bulk_g2s(smem_u32(sW[0]), g_wabT, K1_W_BYTES, barW[0]);
        MBAR_EXPECT_TX(barW[1], K1_W_BYTES);
        bulk_g2s(smem_u32(sW[1]), g_wabT + (size_t)320 * 72, K1_W_BYTES, barW[1]);
    }
    __syncthreads();
    MBAR_WAIT(barE, 0);

    float acc[2][5][4];
#pragma unroll
    for (int t = 0; t < 2; t++)
#pragma unroll
        for (int l = 0; l < 5; l++)
#pragma unroll
            for (int u = 0; u < 4; u++) acc[t][l][u] = 0.f;

    const uint32_t* e0p = sE + (size_t)gq * EPITCH;
    const uint32_t* e1p = e0p + 8 * EPITCH;
    const uint32_t* e2p = e0p + 16 * EPITCH;
    const uint32_t* e3p = e0p + 24 * EPITCH;

    for (int c = 0; c < 12; c++) {
        MBAR_WAIT(barW[c & 1], (c >> 1) & 1);
        const uint32_t* Wb = sW[c & 1];
#pragma unroll
        for (int ks = 0; ks < 4; ks++) {
            int kb = c * 32 + ks * 8 + 2 * qq;
            uint2 e0 = *(const uint2*)(e0p + kb);
            uint2 e1 = *(const uint2*)(e1p + kb);
            uint2 e2 = *(const uint2*)(e2p + kb);
            uint2 e3 = *(const uint2*)(e3p + kb);
            uint32_t a0[4] = { e0.x, e1.x, e0.y, e1.y };
            uint32_t a1[4] = { e2.x, e3.x, e2.y, e3.y };
#pragma unroll
            for (int l = 0; l < 5; l++) {
                int nrow = (w * 5 + l) * 8 + gq;
                uint32_t b[2] = { Wb[nrow * WABPITCH + ks * 8 + qq],
                                  Wb[nrow * WABPITCH + ks * 8 + qq + 4] };
                mma16816(acc[0][l], a0, b, acc[0][l]);
                mma16816(acc[1][l], a1, b, acc[1][l]);
            }
        }
        __syncthreads();
        if (tid == 0 && c + 2 < 12) {
            MBAR_EXPECT_TX(barW[c & 1], K1_W_BYTES);
            bulk_g2s(smem_u32(sW[c & 1]), g_wabT + (size_t)(c + 2) * 320 * 72,
                     K1_W_BYTES, barW[c & 1]);
        }
    }

#pragma unroll
    for (int t = 0; t < 2; t++)
#pragma unroll
        for (int l = 0; l < 5; l++) {
            int n0 = (w * 5 + l) * 8 + 2 * qq;
            int ra = r0 + 16 * t + gq, rb = ra + 8;
#pragma unroll
            for (int u = 0; u < 4; u++) {
                int row = (u < 2) ? ra : rb;
                int n = n0 + (u & 1);
                float v = acc[t][l][u];
                if (n < 160) { if (n < HH) g_A[(size_t)row * APITCH + n] = v + __ldg(b1 + n); }
                else { int h = n - 160; if (h < HH) g_B[(size_t)row * APITCH + h] = v; }
            }
        }
}

// ---------------- k2: fused pair MLP ----------------
// Compact grid (108, 8). 384 thr = 12 warps: mh=w>>1 (0..5, m32), nh=w&1 (n80 half).
// Tile: TI=24 i-rows x TJ=8 j-rows = 192 pairs.
#define K2_EI_OFF   0                                  // 24*392*4 = 37632
#define K2_EJ_OFF   37632                              // 8*392*4  = 12544
#define K2_W_OFF    50176                              // 2 x 45056
#define K2_H1_OFF   140288                             // 192*88*4 = 67584
#define K2_SA_OFF   207872                             // 24*152*4 = 14592
#define K2_SB_OFF   222464                             // 8*152*4  = 4864
#define K2_SC_OFF   227328                             // 192*4    = 768
#define K2_BAR_OFF  228096
#define K2_SMEM     (K2_BAR_OFF + 64)                  // 228160

__global__ __launch_bounds__(384, 1)
void k2_mma(const float* __restrict__ b2,
            const float* __restrict__ W3,
            const float* __restrict__ b3) {
    // decode compact tile index: cum(ti) = 3*ti*(ti+1)/2, tj in [0, 3ti+2]
    const int bz = blockIdx.y;
    int x = blockIdx.x;
    int ti = 0;
#pragma unroll 8
    for (int t = 1; t < 8; t++)
        if (3 * t * (t + 1) / 2 <= x) ti = t;
    const int tj = x - 3 * ti * (ti + 1) / 2;

    extern __shared__ __align__(128) char smem[];
    uint32_t* sEi = (uint32_t*)(smem + K2_EI_OFF);
    uint32_t* sEj = (uint32_t*)(smem + K2_EJ_OFF);
    uint32_t* sW[2] = { (uint32_t*)(smem + K2_W_OFF),
                        (uint32_t*)(smem + K2_W_OFF + W1C_CHUNK_W * 4) };
    uint32_t* sH1 = (uint32_t*)(smem + K2_H1_OFF);
    float*    sSA = (float*)(smem + K2_SA_OFF);
    float*    sSB = (float*)(smem + K2_SB_OFF);
    float*    sSc = (float*)(smem + K2_SC_OFF);
    const uint32_t barE = smem_u32(smem + K2_BAR_OFF);
    const uint32_t barW[2] = { barE + 8, barE + 16 };
    const int tid = threadIdx.x, w = tid >> 5, lane = tid & 31;
    const int mh = w >> 1, nh = w & 1;
    const int gq = lane >> 2, qq = lane & 3;

    if (tid == 0) {
        MBAR_INIT(barE, 1); MBAR_INIT(barW[0], 1); MBAR_INIT(barW[1], 1);
        FENCE_ASYNC();
        MBAR_EXPECT_TX(barE, (24 + 8) * EPITCH * 4);
        bulk_g2s(smem_u32(sEi), g_Ebf + ((size_t)bz * 192 + ti * 24) * EPITCH, 24 * EPITCH * 4, barE);
        bulk_g2s(smem_u32(sEj), g_Ebf + ((size_t)bz * 192 + tj * 8) * EPITCH, 8 * EPITCH * 4, barE);
        MBAR_EXPECT_TX(barW[0], W1C_CHUNK_W * 4);
        bulk_g2s(smem_u32(sW[0]), g_w1cP, W1C_CHUNK_W * 4, barW[0]);
        MBAR_EXPECT_TX(barW[1], W1C_CHUNK_W * 4);
        bulk_g2s(smem_u32(sW[1]), g_w1cP + W1C_CHUNK_W, W1C_CHUNK_W * 4, barW[1]);
    }

    // stage seeds (fp32, coalesced float4) — consumed in epilogue 1 (after chunk syncs)
    {
        const float4* gA4 = (const float4*)(g_A + ((size_t)bz * 192 + ti * 24) * APITCH);
        const float4* gB4 = (const float4*)(g_B + ((size_t)bz * 192 + tj * 8) * APITCH);
        float4* dA = (float4*)sSA;
        float4* dB = (float4*)sSB;
        for (int idx = tid; idx < 24 * 38; idx += 384) dA[idx] = gA4[idx];
        for (int idx = tid; idx < 8 * 38; idx += 384) dB[idx] = gB4[idx];
    }
    __syncthreads();
    MBAR_WAIT(barE, 0);

    float acc[2][10][4];
#pragma unroll
    for (int t = 0; t < 2; t++)
#pragma unroll
        for (int l = 0; l < 10; l++)
#pragma unroll
            for (int u = 0; u < 4; u++) acc[t][l][u] = 0.f;

    const uint32_t* eI0 = sEi + (size_t)(4 * mh + 0) * EPITCH;
    const uint32_t* eI1 = sEi + (size_t)(4 * mh + 1) * EPITCH;
    const uint32_t* eI2 = sEi + (size_t)(4 * mh + 2) * EPITCH;
    const uint32_t* eI3 = sEi + (size_t)(4 * mh + 3) * EPITCH;
    const uint32_t* eJp = sEj + (size_t)gq * EPITCH;
    const int bw_off = lane * 44 + nh * 20;

    // ---- layer 1: 6 K-chunks of 128 ----
    int wp0 = 0, wp1 = 0;
    for (int c = 0; c < 6; c++) {
        if ((c & 1) == 0) { MBAR_WAIT(barW[0], wp0 & 1); wp0++; }
        else              { MBAR_WAIT(barW[1], wp1 & 1); wp1++; }
        const uint32_t* Wb = sW[c & 1];
#pragma unroll 4
        for (int ks = 0; ks < 8; ks++) {
            int kb = c * 64 + ks * 8 + 2 * qq;
            uint2 ej = *(const uint2*)(eJp + kb);
            uint2 e0 = *(const uint2*)(eI0 + kb);
            uint2 e1 = *(const uint2*)(eI1 + kb);
            uint2 e2 = *(const uint2*)(eI2 + kb);
            uint2 e3 = *(const uint2*)(eI3 + kb);
            uint32_t a0[4] = { bmul2(e0.x, ej.x), bmul2(e1.x, ej.x),
                               bmul2(e0.y, ej.y), bmul2(e1.y, ej.y) };
            uint32_t a1[4] = { bmul2(e2.x, ej.x), bmul2(e3.x, ej.x),
                               bmul2(e2.y, ej.y), bmul2(e3.y, ej.y) };
            const uint32_t* bp = Wb + ks * PKS + bw_off;
#pragma unroll
            for (int m = 0; m < 5; m++) {
                uint4 bb = *(const uint4*)(bp + m * 4);
                uint32_t b0[2] = { bb.x, bb.y };
                uint32_t b1r[2] = { bb.z, bb.w };
                mma16816(acc[0][2 * m],     a0, b0,  acc[0][2 * m]);
                mma16816(acc[1][2 * m],     a1, b0,  acc[1][2 * m]);
                mma16816(acc[0][2 * m + 1], a0, b1r, acc[0][2 * m + 1]);
                mma16816(acc[1][2 * m + 1], a1, b1r, acc[1][2 * m + 1]);
            }
        }
        __syncthreads();
        if (tid == 0) {
            if (c + 2 < 6) {
                MBAR_EXPECT_TX(barW[c & 1], W1C_CHUNK_W * 4);
                bulk_g2s(smem_u32(sW[c & 1]), g_w1cP + (size_t)(c + 2) * W1C_CHUNK_W,
                         W1C_CHUNK_W * 4, barW[c & 1]);
            } else if (c == 4) {   // buf0 free: W2 slab A
                MBAR_EXPECT_TX(barW[0], W2_SLAB_W * 4);
                bulk_g2s(smem_u32(sW[0]), g_w2P, W2_SLAB_W * 4, barW[0]);
            } else {               // c == 5, buf1 free: W2 slab B
                MBAR_EXPECT_TX(barW[1], W2_SLAB_W * 4);
                bulk_g2s(smem_u32(sW[1]), g_w2P + W2_SLAB_W, W2_SLAB_W * 4, barW[1]);
            }
        }
    }

    // ---- epilogue 1: + seeds (smem), ReLU, bf16 -> sH1 ----
    const float* sbj = sSB + gq * APITCH;
#pragma unroll
    for (int t = 0; t < 2; t++) {
        const float* sa0 = sSA + (4 * mh + 2 * t) * APITCH;
        const float* sa1 = sa0 + APITCH;
#pragma unroll
        for (int l = 0; l < 10; l++) {
            int nbg = nh * 10 + l;
            int h0 = nbg * 8 + 2 * qq;
            float v0 = 0.f, v1 = 0.f, v2 = 0.f, v3 = 0.f;
            if (h0 < HH) {
                float2 a0v = *(const float2*)(sa0 + h0);
                float2 a1v = *(const float2*)(sa1 + h0);
                float2 bjv = *(const float2*)(sbj + h0);
                v0 = fmaxf(acc[t][l][0] + a0v.x + bjv.x, 0.f);
                v1 = fmaxf(acc[t][l][1] + a0v.y + bjv.y, 0.f);
                v2 = fmaxf(acc[t][l][2] + a1v.x + bjv.x, 0.f);
                v3 = fmaxf(acc[t][l][3] + a1v.y + bjv.y, 0.f);
            }
            int kw = nbg * 4 + qq;
            int ilvw = ((kw >> 3) << 3) + 2 * (kw & 3) + ((kw >> 2) & 1);
            sH1[(32 * mh + 16 * t + gq) * H1PITCH + ilvw]     = packbf(v0, v1);
            sH1[(32 * mh + 16 * t + 8 + gq) * H1PITCH + ilvw] = packbf(v2, v3);
        }
    }
    NBAR(1 + mh, 64);          // mh-pair exchange: h1 halves

    // ---- layer 2: K=160; ks 0..4 from buf0 (slab A), 5..9 from buf1 (slab B) ----
    float ac2[2][10][4];
#pragma unroll
    for (int t = 0; t < 2; t++)
#pragma unroll
        for (int l = 0; l < 10; l++)
#pragma unroll
            for (int u = 0; u < 4; u++) ac2[t][l][u] = 0.f;

    const uint32_t* h0p = sH1 + (size_t)(32 * mh + gq) * H1PITCH;
    const uint32_t* h1p = h0p + 8 * H1PITCH;
    const uint32_t* h2p = h0p + 16 * H1PITCH;
    const uint32_t* h3p = h0p + 24 * H1PITCH;

    MBAR_WAIT(barW[0], wp0 & 1);
#pragma unroll
    for (int half = 0; half < 2; half++) {
        if (half == 1) MBAR_WAIT(barW[1], wp1 & 1);
        const uint32_t* Wb = sW[half];
#pragma unroll
        for (int s = 0; s < 5; s++) {
            int ks = half * 5 + s;
            int kb = ks * 8 + 2 * qq;
            uint2 x0 = *(const uint2*)(h0p + kb);
            uint2 x1 = *(const uint2*)(h1p + kb);
            uint2 x2 = *(const uint2*)(h2p + kb);
            uint2 x3 = *(const uint2*)(h3p + kb);
            uint32_t a0[4] = { x0.x, x1.x, x0.y, x1.y };
            uint32_t a1[4] = { x2.x, x3.x, x2.y, x3.y };
            const uint32_t* bp = Wb + s * PKS + bw_off;
#pragma unroll
            for (int m = 0; m < 5; m++) {
                uint4 bb = *(const uint4*)(bp + m * 4);
                uint32_t b0[2] = { bb.x, bb.y };
                uint32_t b1r[2] = { bb.z, bb.w };
                mma16816(ac2[0][2 * m],     a0, b0,  ac2[0][2 * m]);
                mma16816(ac2[1][2 * m],     a1, b0,  ac2[1][2 * m]);
                mma16816(ac2[0][2 * m + 1], a0, b1r, ac2[0][2 * m + 1]);
                mma16816(ac2[1][2 * m + 1], a1, b1r, ac2[1][2 * m + 1]);
            }
        }
    }

    // ---- epilogue 2: +b2, ReLU, dot W3; mh-pair exchange via sSc + named bar ----
    float sp[2][2] = { {0.f, 0.f}, {0.f, 0.f} };
#pragma unroll
    for (int t = 0; t < 2; t++)
#pragma unroll
        for (int l = 0; l < 10; l++) {
            int h0 = (nh * 10 + l) * 8 + 2 * qq;
            if (h0 < HH) {
                float2 bv = *(const float2*)(b2 + h0);
                float2 wv = *(const float2*)(W3 + h0);
                sp[t][0] += fmaxf(ac2[t][l][0] + bv.x, 0.f) * wv.x
                          + fmaxf(ac2[t][l][1] + bv.y, 0.f) * wv.y;
                sp[t][1] += fmaxf(ac2[t][l][2] + bv.x, 0.f) * wv.x
                          + fmaxf(ac2[t][l][3] + bv.y, 0.f) * wv.y;
            }
        }
#pragma unroll
    for (int t = 0; t < 2; t++)
#pragma unroll
        for (int s = 0; s < 2; s++) {
            sp[t][s] += __shfl_xor_sync(0xffffffffu, sp[t][s], 1);
            sp[t][s] += __shfl_xor_sync(0xffffffffu, sp[t][s], 2);
        }
    if (nh == 0 && qq == 0) {
#pragma unroll
        for (int t = 0; t < 2; t++)
#pragma unroll
            for (int s = 0; s < 2; s++)
                sSc[32 * mh + 16 * t + 8 * s + gq] = sp[t][s];
    }
    NBAR(7 + mh, 64);
    if (nh == 1 && qq == 0) {
        float b3v = __ldg(b3);
#pragma unroll
        for (int t = 0; t < 2; t++)
#pragma unroll
            for (int s = 0; s < 2; s++) {
                int r = 32 * mh + 16 * t + 8 * s + gq;
                int ip = ti * 24 + (r >> 3), jp = tj * 8 + (r & 7);
                if (jp < ip)
                    g_S[((size_t)bz * 192 + ip) * 192 + jp] = sp[t][s] + sSc[r] + b3v;
            }
    }
}

// ---------------- k3: tril softmax ----------------
__global__ void k3_softmax(float* __restrict__ out) {
    const int i = blockIdx.x, b = blockIdx.y, j = threadIdx.x;
    float val;
    if (j < i)       val = g_S[((size_t)b * 192 + i) * 192 + j];
    else if (j == i) val = 0.f;
    else             val = -1e30f;

    __shared__ float red[6];
    float m = val;
#pragma unroll
    for (int o = 16; o; o >>= 1) m = fmaxf(m, __shfl_xor_sync(0xffffffffu, m, o));
    if ((j & 31) == 0) red[j >> 5] = m;
    __syncthreads();
    float M = fmaxf(fmaxf(fmaxf(red[0], red[1]), fmaxf(red[2], red[3])), fmaxf(red[4], red[5]));
    __syncthreads();
    float e = (j <= i) ? expf(val - M) : 0.f;
    float s = e;
#pragma unroll
    for (int o = 16; o; o >>= 1) s += __shfl_xor_sync(0xffffffffu, s, o);
    if ((j & 31) == 0) red[j >> 5] = s;
    __syncthreads();
    float S = red[0] + red[1] + red[2] + red[3] + red[4] + red[5];
    out[((size_t)b * 192 + i) * 192 + j] = (j <= i) ? (e / S) : -1000.0f;
}

// ---------------------------------------------------------------------------
extern "C" void kernel_launch(void* const* d_in, const int* in_sizes, int n_in,
                              void* d_out, int out_size) {
    const float* E  = (const float*)d_in[0];
    const float* W1 = (const float*)d_in[1];
    const float* b1 = (const float*)d_in[2];
    const float* W2 = (const float*)d_in[3];
    const float* b2 = (const float*)d_in[4];
    const float* W3 = (const float*)d_in[5];
    const float* b3 = (const float*)d_in[6];
    float* out = (float*)d_out;

    cudaFuncSetAttribute(k1_mma, cudaFuncAttributeMaxDynamicSharedMemorySize, K1_SMEM);
    cudaFuncSetAttribute(k2_mma, cudaFuncAttributeMaxDynamicSharedMemorySize, K2_SMEM);

    kprep_e<<<(1536 * EPITCH + 255) / 256, 256>>>(E);
    kprep_w<<<(WAB_N + W1CP_N + W2_W + 255) / 256, 256>>>(W1, W2);
    k1_mma<<<48, 256, K1_SMEM>>>(b1);
    k2_mma<<<dim3(108, 8), 384, K2_SMEM>>>(b2, W3, b3);
    k3_softmax<<<dim3(192, 8), 192>>>(out);
}

// round 6
// speedup vs baseline: 1.0860x; 1.0860x over previous
#include <cuda_runtime.h>
#include <cuda_bf16.h>
#include <cstdint>

#define HH 150
#define APITCH 152          // g_A/g_B row pitch (floats)

#define EPITCH 392          // E row pitch in u32 words
#define H1PITCH 88          // h1 row pitch in u32 words
#define WABPITCH 36         // k1 weight row pitch (u32 words)

// Packed-fragment W blob geometry: per k16-step: 32 lanes * 44 words
#define PKS 1408
#define W1C_CHUNK_W 11264   // 8 ks (K=128 chunk)
#define W2_W 14080          // 10 ks (K=160)
#define W2_SLAB_W 7040      // 5 ks

// ---------------- device scratch ----------------
__device__ __align__(16) uint32_t      g_Ebf[1536 * EPITCH];
__device__ __align__(16) __nv_bfloat16 g_wabT[12 * 320 * 72];
__device__ __align__(16) uint32_t      g_w1cP[6 * W1C_CHUNK_W];
__device__ __align__(16) uint32_t      g_w2P[W2_W];
__device__ __align__(16) float g_A[1536 * APITCH];
__device__ __align__(16) float g_B[1536 * APITCH];
__device__ float g_S[8 * 192 * 192];

// ---------------- helpers ----------------
__device__ __forceinline__ uint32_t smem_u32(const void* p) {
    uint32_t a;
    asm("{ .reg .u64 t; cvta.to.shared.u64 t, %1; cvt.u32.u64 %0, t; }" : "=r"(a) : "l"(p));
    return a;
}
__device__ __forceinline__ uint32_t packbf(float lo, float hi) {
    uint32_t d; asm("cvt.rn.bf16x2.f32 %0, %1, %2;" : "=r"(d) : "f"(hi), "f"(lo)); return d;
}
__device__ __forceinline__ uint32_t bmul2(uint32_t a, uint32_t b) {
    uint32_t d; asm("mul.rn.bf16x2 %0, %1, %2;" : "=r"(d) : "r"(a), "r"(b)); return d;
}
__device__ __forceinline__ void mma16816(float* d, const uint32_t* a, const uint32_t* b,
                                         const float* c) {
    asm volatile(
        "mma.sync.aligned.m16n8k16.row.col.f32.bf16.bf16.f32 "
        "{%0,%1,%2,%3}, {%4,%5,%6,%7}, {%8,%9}, {%10,%11,%12,%13};"
        : "=f"(d[0]), "=f"(d[1]), "=f"(d[2]), "=f"(d[3])
        : "r"(a[0]), "r"(a[1]), "r"(a[2]), "r"(a[3]), "r"(b[0]), "r"(b[1]),
          "f"(c[0]), "f"(c[1]), "f"(c[2]), "f"(c[3]));
}
#define MBAR_INIT(mb, cnt) asm volatile("mbarrier.init.shared.b64 [%0], %1;" :: "r"((uint32_t)(mb)), "r"((uint32_t)(cnt)) : "memory")
#define MBAR_EXPECT_TX(mb, n) asm volatile("mbarrier.arrive.expect_tx.shared.b64 _, [%0], %1;" :: "r"((uint32_t)(mb)), "r"((uint32_t)(n)) : "memory")
#define MBAR_ARRIVE(mb) asm volatile("mbarrier.arrive.release.cta.shared::cta.b64 _, [%0];" :: "r"((uint32_t)(mb)) : "memory")
#define FENCE_ASYNC() asm volatile("fence.proxy.async.shared::cta;" ::: "memory")
#define NBAR(id, cnt) asm volatile("bar.sync %0, %1;" :: "r"(id), "r"(cnt) : "memory")
#define MBAR_WAIT(mb, ph) do { \
    uint32_t _m = (uint32_t)(mb); uint32_t _p = (uint32_t)(ph); uint32_t _d; \
    asm volatile("{\n\t.reg .pred p;\n\tmbarrier.try_wait.parity.acquire.cta.shared::cta.b64 p, [%1], %2;\n\tselp.b32 %0, 1, 0, p;\n\t}" \
        : "=r"(_d) : "r"(_m), "r"(_p) : "memory"); \
    if (!_d) { \
        asm volatile("{\n\t.reg .pred P1;\n\tWL_%=:\n\tmbarrier.try_wait.parity.acquire.cta.shared::cta.b64 P1, [%0], %1, 0x989680;\n\t@P1 bra.uni WD_%=;\n\tbra.uni WL_%=;\n\tWD_%=:\n\t}" \
            :: "r"(_m), "r"(_p) : "memory"); \
    } } while (0)
__device__ __forceinline__ void bulk_g2s(uint32_t dst, const void* src, uint32_t bytes, uint32_t mbar) {
    asm volatile("cp.async.bulk.shared::cta.global.mbarrier::complete_tx::bytes [%0], [%1], %2, [%3];"
        :: "r"(dst), "l"(src), "r"(bytes), "r"(mbar) : "memory");
}

// ---------------- prep: E -> interleaved bf16x2 ----------------
__global__ void kprep_e(const float* __restrict__ E) {
    int idx = blockIdx.x * 256 + threadIdx.x;
    if (idx >= 1536 * EPITCH) return;
    int r = idx / EPITCH, pos = idx % EPITCH;
    int g = pos >> 3, wi = pos & 7, q = wi >> 1, h = wi & 1;
    int kw = g * 8 + q + 4 * h;
    uint32_t v = 0;
    if (kw < 384) {
        float2 e = *reinterpret_cast<const float2*>(E + (size_t)r * 768 + 2 * kw);
        v = packbf(e.x, e.y);
    }
    g_Ebf[idx] = v;
}

// ---------------- prep: weights ----------------
#define WAB_N (12 * 320 * 72)
#define W1CP_N (6 * W1C_CHUNK_W)
__global__ void kprep_w(const float* __restrict__ W1, const float* __restrict__ W2) {
    int idx = blockIdx.x * 256 + threadIdx.x;
    if (idx < WAB_N) {
        int c = idx / (320 * 72), rem = idx % (320 * 72);
        int n = rem / 72, kk = rem % 72;
        float v = 0.f;
        if (kk < 64) {
            int kg = c * 64 + kk;
            if (n < 160) { if (n < HH) v = W1[(size_t)kg * HH + n]; }
            else { int h = n - 160; if (h < HH) v = W1[(size_t)(768 + kg) * HH + h]; }
        }
        g_wabT[idx] = __float2bfloat16(v);
    } else if (idx < WAB_N + W1CP_N + W2_W) {
        int t = idx - WAB_N;
        bool isW2 = (t >= W1CP_N);
        int c = 0, r;
        if (isW2) r = t - W1CP_N;
        else { c = t / W1C_CHUNK_W; r = t % W1C_CHUNK_W; }
        int ks = r / PKS, r1 = r % PKS;
        int lane = r1 / 44, r2 = r1 % 44;
        uint32_t v = 0;
        if (r2 < 40) {
            int nh = r2 / 20, r3 = r2 % 20, m = r3 / 4, e = r3 % 4;
            int gq = lane >> 2, qq = lane & 3;
            int nb = nh * 10 + 2 * m + (e >> 1);
            int kwl = ks * 8 + qq + (e & 1) * 4;
            int n = nb * 8 + gq;
            float v0 = 0.f, v1 = 0.f;
            if (n < HH) {
                if (isW2) {
                    int k0 = 2 * kwl;
                    if (k0 < HH)     v0 = W2[(size_t)k0 * HH + n];
                    if (k0 + 1 < HH) v1 = W2[(size_t)(k0 + 1) * HH + n];
                } else {
                    int k0 = c * 128 + 2 * kwl;
                    v0 = W1[(size_t)(1536 + k0) * HH + n];
                    v1 = W1[(size_t)(1536 + k0 + 1) * HH + n];
                }
            }
            v = packbf(v0, v1);
        }
        if (isW2) g_w2P[r] = v; else g_w1cP[(size_t)c * W1C_CHUNK_W + r] = v;
    }
}

// ---------------- k1: seeds GEMM -> g_A,g_B (pitch 152) ----------------
#define K1_E_BYTES (32 * EPITCH * 4)
#define K1_W_BYTES (320 * WABPITCH * 4)
#define K1_BAR_OFF (K1_E_BYTES + 2 * K1_W_BYTES)
#define K1_SMEM    (K1_BAR_OFF + 64)

__global__ __launch_bounds__(256, 1)
void k1_mma(const float* __restrict__ b1) {
    extern __shared__ __align__(128) char smem[];
    uint32_t* sE = (uint32_t*)smem;
    uint32_t* sW[2] = { (uint32_t*)(smem + K1_E_BYTES),
                        (uint32_t*)(smem + K1_E_BYTES + K1_W_BYTES) };
    const uint32_t barE = smem_u32(smem + K1_BAR_OFF);
    const uint32_t barW[2] = { barE + 8, barE + 16 };
    const int tid = threadIdx.x, w = tid >> 5, lane = tid & 31;
    const int gq = lane >> 2, qq = lane & 3;
    const int r0 = blockIdx.x * 32;

    if (tid == 0) {
        MBAR_INIT(barE, 1); MBAR_INIT(barW[0], 1); MBAR_INIT(barW[1], 1);
        FENCE_ASYNC();
        MBAR_EXPECT_TX(barE, K1_E_BYTES);
        bulk_g2s(smem_u32(sE), g_Ebf + (size_t)r0 * EPITCH, K1_E_BYTES, barE);
        MBAR_EXPECT_TX(barW[0], K1_W_BYTES);
        bulk_g2s(smem_u32(sW[0]), g_wabT, K1_W_BYTES, barW[0]);
        MBAR_EXPECT_TX(barW[1], K1_W_BYTES);
        bulk_g2s(smem_u32(sW[1]), g_wabT + (size_t)320 * 72, K1_W_BYTES, barW[1]);
    }
    __syncthreads();
    MBAR_WAIT(barE, 0);

    float acc[2][5][4];
#pragma unroll
    for (int t = 0; t < 2; t++)
#pragma unroll
        for (int l = 0; l < 5; l++)
#pragma unroll
            for (int u = 0; u < 4; u++) acc[t][l][u] = 0.f;

    const uint32_t* e0p = sE + (size_t)gq * EPITCH;
    const uint32_t* e1p = e0p + 8 * EPITCH;
    const uint32_t* e2p = e0p + 16 * EPITCH;
    const uint32_t* e3p = e0p + 24 * EPITCH;

    for (int c = 0; c < 12; c++) {
        MBAR_WAIT(barW[c & 1], (c >> 1) & 1);
        const uint32_t* Wb = sW[c & 1];
#pragma unroll
        for (int ks = 0; ks < 4; ks++) {
            int kb = c * 32 + ks * 8 + 2 * qq;
            uint2 e0 = *(const uint2*)(e0p + kb);
            uint2 e1 = *(const uint2*)(e1p + kb);
            uint2 e2 = *(const uint2*)(e2p + kb);
            uint2 e3 = *(const uint2*)(e3p + kb);
            uint32_t a0[4] = { e0.x, e1.x, e0.y, e1.y };
            uint32_t a1[4] = { e2.x, e3.x, e2.y, e3.y };
#pragma unroll
            for (int l = 0; l < 5; l++) {
                int nrow = (w * 5 + l) * 8 + gq;
                uint32_t b[2] = { Wb[nrow * WABPITCH + ks * 8 + qq],
                                  Wb[nrow * WABPITCH + ks * 8 + qq + 4] };
                mma16816(acc[0][l], a0, b, acc[0][l]);
                mma16816(acc[1][l], a1, b, acc[1][l]);
            }
        }
        __syncthreads();
        if (tid == 0 && c + 2 < 12) {
            MBAR_EXPECT_TX(barW[c & 1], K1_W_BYTES);
            bulk_g2s(smem_u32(sW[c & 1]), g_wabT + (size_t)(c + 2) * 320 * 72,
                     K1_W_BYTES, barW[c & 1]);
        }
    }

#pragma unroll
    for (int t = 0; t < 2; t++)
#pragma unroll
        for (int l = 0; l < 5; l++) {
            int n0 = (w * 5 + l) * 8 + 2 * qq;
            int ra = r0 + 16 * t + gq, rb = ra + 8;
#pragma unroll
            for (int u = 0; u < 4; u++) {
                int row = (u < 2) ? ra : rb;
                int n = n0 + (u & 1);
                float v = acc[t][l][u];
                if (n < 160) { if (n < HH) g_A[(size_t)row * APITCH + n] = v + __ldg(b1 + n); }
                else { int h = n - 160; if (h < HH) g_B[(size_t)row * APITCH + h] = v; }
            }
        }
}

// ---------------- k2: fused pair MLP (decoupled mainloop) ----------------
// Compact grid (108, 8). 384 thr = 12 warps: mh=w>>1 (0..5, m32), nh=w&1 (n80 half).
#define K2_EI_OFF   0                                  // 24*392*4 = 37632
#define K2_EJ_OFF   37632                              // 8*392*4  = 12544
#define K2_W_OFF    50176                              // 2 x 45056
#define K2_H1_OFF   140288                             // 192*88*4 = 67584
#define K2_SA_OFF   207872                             // 24*152*4 = 14592
#define K2_SB_OFF   222464                             // 8*152*4  = 4864
#define K2_SC_OFF   227328                             // 192*4    = 768
#define K2_BW_OFF   228096                             // b2|W3: 2*152*4 = 1216
#define K2_BAR_OFF  229312
#define K2_SMEM     (K2_BAR_OFF + 64)                  // 229376

__global__ __launch_bounds__(384, 1)
void k2_mma(const float* __restrict__ b2,
            const float* __restrict__ W3,
            const float* __restrict__ b3) {
    const int bz = blockIdx.y;
    int x = blockIdx.x;
    int ti = 0;
#pragma unroll 8
    for (int t = 1; t < 8; t++)
        if (3 * t * (t + 1) / 2 <= x) ti = t;
    const int tj = x - 3 * ti * (ti + 1) / 2;

    extern __shared__ __align__(128) char smem[];
    uint32_t* sEi = (uint32_t*)(smem + K2_EI_OFF);
    uint32_t* sEj = (uint32_t*)(smem + K2_EJ_OFF);
    uint32_t* sW[2] = { (uint32_t*)(smem + K2_W_OFF),
                        (uint32_t*)(smem + K2_W_OFF + W1C_CHUNK_W * 4) };
    uint32_t* sH1 = (uint32_t*)(smem + K2_H1_OFF);
    float*    sSA = (float*)(smem + K2_SA_OFF);
    float*    sSB = (float*)(smem + K2_SB_OFF);
    float*    sSc = (float*)(smem + K2_SC_OFF);
    float*    sB2 = (float*)(smem + K2_BW_OFF);
    float*    sW3 = sB2 + 152;
    const uint32_t barE = smem_u32(smem + K2_BAR_OFF);
    const uint32_t barW[2] = { barE + 8, barE + 16 };
    const uint32_t barC[2] = { barE + 24, barE + 32 };
    const int tid = threadIdx.x, w = tid >> 5, lane = tid & 31;
    const int mh = w >> 1, nh = w & 1;
    const int gq = lane >> 2, qq = lane & 3;

    if (tid == 0) {
        MBAR_INIT(barE, 1); MBAR_INIT(barW[0], 1); MBAR_INIT(barW[1], 1);
        MBAR_INIT(barC[0], 12); MBAR_INIT(barC[1], 12);
        FENCE_ASYNC();
        MBAR_EXPECT_TX(barE, (24 + 8) * EPITCH * 4);
        bulk_g2s(smem_u32(sEi), g_Ebf + ((size_t)bz * 192 + ti * 24) * EPITCH, 24 * EPITCH * 4, barE);
        bulk_g2s(smem_u32(sEj), g_Ebf + ((size_t)bz * 192 + tj * 8) * EPITCH, 8 * EPITCH * 4, barE);
        MBAR_EXPECT_TX(barW[0], W1C_CHUNK_W * 4);
        bulk_g2s(smem_u32(sW[0]), g_w1cP, W1C_CHUNK_W * 4, barW[0]);
        MBAR_EXPECT_TX(barW[1], W1C_CHUNK_W * 4);
        bulk_g2s(smem_u32(sW[1]), g_w1cP + W1C_CHUNK_W, W1C_CHUNK_W * 4, barW[1]);
    }

    // stage seeds + b2/W3 (coalesced LDG -> smem), consumed after mainloop
    {
        const float4* gA4 = (const float4*)(g_A + ((size_t)bz * 192 + ti * 24) * APITCH);
        const float4* gB4 = (const float4*)(g_B + ((size_t)bz * 192 + tj * 8) * APITCH);
        float4* dA = (float4*)sSA;
        float4* dB = (float4*)sSB;
        for (int idx = tid; idx < 24 * 38; idx += 384) dA[idx] = gA4[idx];
        for (int idx = tid; idx < 8 * 38; idx += 384) dB[idx] = gB4[idx];
        if (tid < 152) { sB2[tid] = (tid < HH) ? b2[tid] : 0.f; }
        else if (tid < 304) { int h = tid - 152; sW3[h] = (h < HH) ? W3[h] : 0.f; }
    }
    __syncthreads();   // mbar inits + seed staging visible block-wide
    MBAR_WAIT(barE, 0);

    float acc[2][10][4];
#pragma unroll
    for (int t = 0; t < 2; t++)
#pragma unroll
        for (int l = 0; l < 10; l++)
#pragma unroll
            for (int u = 0; u < 4; u++) acc[t][l][u] = 0.f;

    const uint32_t* eI0 = sEi + (size_t)(4 * mh + 0) * EPITCH;
    const uint32_t* eI1 = sEi + (size_t)(4 * mh + 1) * EPITCH;
    const uint32_t* eI2 = sEi + (size_t)(4 * mh + 2) * EPITCH;
    const uint32_t* eI3 = sEi + (size_t)(4 * mh + 3) * EPITCH;
    const uint32_t* eJp = sEj + (size_t)gq * EPITCH;
    const int bw_off = lane * 44 + nh * 20;

    // ---- layer 1: 6 K-chunks of 128, decoupled producer/consumer ----
    int wp0 = 0, wp1 = 0;      // full-bar phases
    int cp0 = 0, cp1 = 0;      // consumed-bar phases (issuer only)
    for (int c = 0; c < 6; c++) {
        const int buf = c & 1;
        if (buf == 0) { MBAR_WAIT(barW[0], wp0 & 1); wp0++; }
        else          { MBAR_WAIT(barW[1], wp1 & 1); wp1++; }
        const uint32_t* Wb = sW[buf];
#pragma unroll 4
        for (int ks = 0; ks < 8; ks++) {
            int kb = c * 64 + ks * 8 + 2 * qq;
            uint2 ej = *(const uint2*)(eJp + kb);
            uint2 e0 = *(const uint2*)(eI0 + kb);
            uint2 e1 = *(const uint2*)(eI1 + kb);
            uint2 e2 = *(const uint2*)(eI2 + kb);
            uint2 e3 = *(const uint2*)(eI3 + kb);
            uint32_t a0[4] = { bmul2(e0.x, ej.x), bmul2(e1.x, ej.x),
                               bmul2(e0.y, ej.y), bmul2(e1.y, ej.y) };
            uint32_t a1[4] = { bmul2(e2.x, ej.x), bmul2(e3.x, ej.x),
                               bmul2(e2.y, ej.y), bmul2(e3.y, ej.y) };
            const uint32_t* bp = Wb + ks * PKS + bw_off;
#pragma unroll
            for (int m = 0; m < 5; m++) {
                uint4 bb = *(const uint4*)(bp + m * 4);
                uint32_t b0[2] = { bb.x, bb.y };
                uint32_t b1r[2] = { bb.z, bb.w };
                mma16816(acc[0][2 * m],     a0, b0,  acc[0][2 * m]);
                mma16816(acc[1][2 * m],     a1, b0,  acc[1][2 * m]);
                mma16816(acc[0][2 * m + 1], a0, b1r, acc[0][2 * m + 1]);
                mma16816(acc[1][2 * m + 1], a1, b1r, acc[1][2 * m + 1]);
            }
        }
        __syncwarp();
        if (lane == 0) MBAR_ARRIVE(barC[buf]);   // this warp done with buf
        if (w == 0 && lane == 0) {
            // issuer: wait all 12 warps consumed buf, then refill it
            if (buf == 0) { MBAR_WAIT(barC[0], cp0 & 1); cp0++; }
            else          { MBAR_WAIT(barC[1], cp1 & 1); cp1++; }
            if (c + 2 < 6) {
                MBAR_EXPECT_TX(barW[buf], W1C_CHUNK_W * 4);
                bulk_g2s(smem_u32(sW[buf]), g_w1cP + (size_t)(c + 2) * W1C_CHUNK_W,
                         W1C_CHUNK_W * 4, barW[buf]);
            } else {   // c==4 -> W2 slab A into buf0; c==5 -> slab B into buf1
                MBAR_EXPECT_TX(barW[buf], W2_SLAB_W * 4);
                bulk_g2s(smem_u32(sW[buf]), g_w2P + (size_t)buf * W2_SLAB_W,
                         W2_SLAB_W * 4, barW[buf]);
            }
        }
    }

    // ---- epilogue 1: + seeds (smem), ReLU, bf16 -> sH1 ----
    const float* sbj = sSB + gq * APITCH;
#pragma unroll
    for (int t = 0; t < 2; t++) {
        const float* sa0 = sSA + (4 * mh + 2 * t) * APITCH;
        const float* sa1 = sa0 + APITCH;
#pragma unroll
        for (int l = 0; l < 10; l++) {
            int nbg = nh * 10 + l;
            int h0 = nbg * 8 + 2 * qq;
            float v0 = 0.f, v1 = 0.f, v2 = 0.f, v3 = 0.f;
            if (h0 < HH) {
                float2 a0v = *(const float2*)(sa0 + h0);
                float2 a1v = *(const float2*)(sa1 + h0);
                float2 bjv = *(const float2*)(sbj + h0);
                v0 = fmaxf(acc[t][l][0] + a0v.x + bjv.x, 0.f);
                v1 = fmaxf(acc[t][l][1] + a0v.y + bjv.y, 0.f);
                v2 = fmaxf(acc[t][l][2] + a1v.x + bjv.x, 0.f);
                v3 = fmaxf(acc[t][l][3] + a1v.y + bjv.y, 0.f);
            }
            int kw = nbg * 4 + qq;
            int ilvw = ((kw >> 3) << 3) + 2 * (kw & 3) + ((kw >> 2) & 1);
            sH1[(32 * mh + 16 * t + gq) * H1PITCH + ilvw]     = packbf(v0, v1);
            sH1[(32 * mh + 16 * t + 8 + gq) * H1PITCH + ilvw] = packbf(v2, v3);
        }
    }
    NBAR(1 + mh, 64);          // nh-pair exchange of h1 halves

    // ---- layer 2: K=160; ks 0..4 from buf0 (slab A), 5..9 from buf1 (slab B) ----
    float ac2[2][10][4];
#pragma unroll
    for (int t = 0; t < 2; t++)
#pragma unroll
        for (int l = 0; l < 10; l++)
#pragma unroll
            for (int u = 0; u < 4; u++) ac2[t][l][u] = 0.f;

    const uint32_t* h0p = sH1 + (size_t)(32 * mh + gq) * H1PITCH;
    const uint32_t* h1p = h0p + 8 * H1PITCH;
    const uint32_t* h2p = h0p + 16 * H1PITCH;
    const uint32_t* h3p = h0p + 24 * H1PITCH;

    MBAR_WAIT(barW[0], wp0 & 1);   // W2 slab A (4th completion on full0)
#pragma unroll
    for (int half = 0; half < 2; half++) {
        if (half == 1) MBAR_WAIT(barW[1], wp1 & 1);
        const uint32_t* Wb = sW[half];
#pragma unroll
        for (int s = 0; s < 5; s++) {
            int ks = half * 5 + s;
            int kb = ks * 8 + 2 * qq;
            uint2 x0 = *(const uint2*)(h0p + kb);
            uint2 x1 = *(const uint2*)(h1p + kb);
            uint2 x2 = *(const uint2*)(h2p + kb);
            uint2 x3 = *(const uint2*)(h3p + kb);
            uint32_t a0[4] = { x0.x, x1.x, x0.y, x1.y };
            uint32_t a1[4] = { x2.x, x3.x, x2.y, x3.y };
            const uint32_t* bp = Wb + s * PKS + bw_off;
#pragma unroll
            for (int m = 0; m < 5; m++) {
                uint4 bb = *(const uint4*)(bp + m * 4);
                uint32_t b0[2] = { bb.x, bb.y };
                uint32_t b1r[2] = { bb.z, bb.w };
                mma16816(ac2[0][2 * m],     a0, b0,  ac2[0][2 * m]);
                mma16816(ac2[1][2 * m],     a1, b0,  ac2[1][2 * m]);
                mma16816(ac2[0][2 * m + 1], a0, b1r, ac2[0][2 * m + 1]);
                mma16816(ac2[1][2 * m + 1], a1, b1r, ac2[1][2 * m + 1]);
            }
        }
    }

    // ---- epilogue 2: +b2, ReLU, dot W3 (all smem); nh-pair exchange via sSc ----
    float sp[2][2] = { {0.f, 0.f}, {0.f, 0.f} };
#pragma unroll
    for (int t = 0; t < 2; t++)
#pragma unroll
        for (int l = 0; l < 10; l++) {
            int h0 = (nh * 10 + l) * 8 + 2 * qq;
            if (h0 < HH) {
                float2 bv = *(const float2*)(sB2 + h0);
                float2 wv = *(const float2*)(sW3 + h0);
                sp[t][0] += fmaxf(ac2[t][l][0] + bv.x, 0.f) * wv.x
                          + fmaxf(ac2[t][l][1] + bv.y, 0.f) * wv.y;
                sp[t][1] += fmaxf(ac2[t][l][2] + bv.x, 0.f) * wv.x
                          + fmaxf(ac2[t][l][3] + bv.y, 0.f) * wv.y;
            }
        }
#pragma unroll
    for (int t = 0; t < 2; t++)
#pragma unroll
        for (int s = 0; s < 2; s++) {
            sp[t][s] += __shfl_xor_sync(0xffffffffu, sp[t][s], 1);
            sp[t][s] += __shfl_xor_sync(0xffffffffu, sp[t][s], 2);
        }
    if (nh == 0 && qq == 0) {
#pragma unroll
        for (int t = 0; t < 2; t++)
#pragma unroll
            for (int s = 0; s < 2; s++)
                sSc[32 * mh + 16 * t + 8 * s + gq] = sp[t][s];
    }
    NBAR(8 + mh, 64);
    if (nh == 1 && qq == 0) {
        float b3v = __ldg(b3);
#pragma unroll
        for (int t = 0; t < 2; t++)
#pragma unroll
            for (int s = 0; s < 2; s++) {
                int r = 32 * mh + 16 * t + 8 * s + gq;
                int ip = ti * 24 + (r >> 3), jp = tj * 8 + (r & 7);
                if (jp < ip)
                    g_S[((size_t)bz * 192 + ip) * 192 + jp] = sp[t][s] + sSc[r] + b3v;
            }
    }
}

// ---------------- k3: tril softmax ----------------
__global__ void k3_softmax(float* __restrict__ out) {
    const int i = blockIdx.x, b = blockIdx.y, j = threadIdx.x;
    float val;
    if (j < i)       val = g_S[((size_t)b * 192 + i) * 192 + j];
    else if (j == i) val = 0.f;
    else             val = -1e30f;

    __shared__ float red[6];
    float m = val;
#pragma unroll
    for (int o = 16; o; o >>= 1) m = fmaxf(m, __shfl_xor_sync(0xffffffffu, m, o));
    if ((j & 31) == 0) red[j >> 5] = m;
    __syncthreads();
    float M = fmaxf(fmaxf(fmaxf(red[0], red[1]), fmaxf(red[2], red[3])), fmaxf(red[4], red[5]));
    __syncthreads();
    float e = (j <= i) ? expf(val - M) : 0.f;
    float s = e;
#pragma unroll
    for (int o = 16; o; o >>= 1) s += __shfl_xor_sync(0xffffffffu, s, o);
    if ((j & 31) == 0) red[j >> 5] = s;
    __syncthreads();
    float S = red[0] + red[1] + red[2] + red[3] + red[4] + red[5];
    out[((size_t)b * 192 + i) * 192 + j] = (j <= i) ? (e / S) : -1000.0f;
}

// ---------------------------------------------------------------------------
extern "C" void kernel_launch(void* const* d_in, const int* in_sizes, int n_in,
                              void* d_out, int out_size) {
    const float* E  = (const float*)d_in[0];
    const float* W1 = (const float*)d_in[1];
    const float* b1 = (const float*)d_in[2];
    const float* W2 = (const float*)d_in[3];
    const float* b2 = (const float*)d_in[4];
    const float* W3 = (const float*)d_in[5];
    const float* b3 = (const float*)d_in[6];
    float* out = (float*)d_out;

    cudaFuncSetAttribute(k1_mma, cudaFuncAttributeMaxDynamicSharedMemorySize, K1_SMEM);
    cudaFuncSetAttribute(k2_mma, cudaFuncAttributeMaxDynamicSharedMemorySize, K2_SMEM);

    kprep_e<<<(1536 * EPITCH + 255) / 256, 256>>>(E);
    kprep_w<<<(WAB_N + W1CP_N + W2_W + 255) / 256, 256>>>(W1, W2);
    k1_mma<<<48, 256, K1_SMEM>>>(b1);
    k2_mma<<<dim3(108, 8), 384, K2_SMEM>>>(b2, W3, b3);
    k3_softmax<<<dim3(192, 8), 192>>>(out);
}

// round 7
// speedup vs baseline: 1.0877x; 1.0016x over previous
#include <cuda_runtime.h>
#include <cuda_bf16.h>
#include <cstdint>

#define HH 150
#define APITCH 152          // g_A/g_B row pitch (floats)

#define EPITCH 392          // E row pitch in u32 words
#define H1PITCH 88          // h1 row pitch in u32 words
#define WABPITCH 36         // k1 weight row pitch (u32 words)

// Packed-fragment W blob geometry: per k16-step: 32 lanes * 44 words
#define PKS 1408
#define W1C_CHUNK_W 11264   // 8 ks (prep-kernel layout unit; storage is ks-contiguous)
#define W2_W 14080          // 10 ks (K=160)

// ---------------- device scratch ----------------
__device__ __align__(16) uint32_t      g_Ebf[1536 * EPITCH];
__device__ __align__(16) __nv_bfloat16 g_wabT[12 * 320 * 72];
__device__ __align__(16) uint32_t      g_w1cP[6 * W1C_CHUNK_W];   // 48 ks contiguous
__device__ __align__(16) uint32_t      g_w2P[W2_W];               // 10 ks contiguous
__device__ __align__(16) float g_A[1536 * APITCH];
__device__ __align__(16) float g_B[1536 * APITCH];
__device__ float g_S[8 * 192 * 192];

// ---------------- helpers ----------------
__device__ __forceinline__ uint32_t smem_u32(const void* p) {
    uint32_t a;
    asm("{ .reg .u64 t; cvta.to.shared.u64 t, %1; cvt.u32.u64 %0, t; }" : "=r"(a) : "l"(p));
    return a;
}
__device__ __forceinline__ uint32_t packbf(float lo, float hi) {
    uint32_t d; asm("cvt.rn.bf16x2.f32 %0, %1, %2;" : "=r"(d) : "f"(hi), "f"(lo)); return d;
}
__device__ __forceinline__ uint32_t bmul2(uint32_t a, uint32_t b) {
    uint32_t d; asm("mul.rn.bf16x2 %0, %1, %2;" : "=r"(d) : "r"(a), "r"(b)); return d;
}
__device__ __forceinline__ void mma16816(float* d, const uint32_t* a, const uint32_t* b,
                                         const float* c) {
    asm volatile(
        "mma.sync.aligned.m16n8k16.row.col.f32.bf16.bf16.f32 "
        "{%0,%1,%2,%3}, {%4,%5,%6,%7}, {%8,%9}, {%10,%11,%12,%13};"
        : "=f"(d[0]), "=f"(d[1]), "=f"(d[2]), "=f"(d[3])
        : "r"(a[0]), "r"(a[1]), "r"(a[2]), "r"(a[3]), "r"(b[0]), "r"(b[1]),
          "f"(c[0]), "f"(c[1]), "f"(c[2]), "f"(c[3]));
}
#define MBAR_INIT(mb, cnt) asm volatile("mbarrier.init.shared.b64 [%0], %1;" :: "r"((uint32_t)(mb)), "r"((uint32_t)(cnt)) : "memory")
#define MBAR_EXPECT_TX(mb, n) asm volatile("mbarrier.arrive.expect_tx.shared.b64 _, [%0], %1;" :: "r"((uint32_t)(mb)), "r"((uint32_t)(n)) : "memory")
#define MBAR_ARRIVE(mb) asm volatile("mbarrier.arrive.release.cta.shared::cta.b64 _, [%0];" :: "r"((uint32_t)(mb)) : "memory")
#define FENCE_ASYNC() asm volatile("fence.proxy.async.shared::cta;" ::: "memory")
#define NBAR(id, cnt) asm volatile("bar.sync %0, %1;" :: "r"(id), "r"(cnt) : "memory")
#define MBAR_WAIT(mb, ph) do { \
    uint32_t _m = (uint32_t)(mb); uint32_t _p = (uint32_t)(ph); uint32_t _d; \
    asm volatile("{\n\t.reg .pred p;\n\tmbarrier.try_wait.parity.acquire.cta.shared::cta.b64 p, [%1], %2;\n\tselp.b32 %0, 1, 0, p;\n\t}" \
        : "=r"(_d) : "r"(_m), "r"(_p) : "memory"); \
    if (!_d) { \
        asm volatile("{\n\t.reg .pred P1;\n\tWL_%=:\n\tmbarrier.try_wait.parity.acquire.cta.shared::cta.b64 P1, [%0], %1, 0x989680;\n\t@P1 bra.uni WD_%=;\n\tbra.uni WL_%=;\n\tWD_%=:\n\t}" \
            :: "r"(_m), "r"(_p) : "memory"); \
    } } while (0)
__device__ __forceinline__ void bulk_g2s(uint32_t dst, const void* src, uint32_t bytes, uint32_t mbar) {
    asm volatile("cp.async.bulk.shared::cta.global.mbarrier::complete_tx::bytes [%0], [%1], %2, [%3];"
        :: "r"(dst), "l"(src), "r"(bytes), "r"(mbar) : "memory");
}

// ---------------- prep: E -> interleaved bf16x2 ----------------
__global__ void kprep_e(const float* __restrict__ E) {
    int idx = blockIdx.x * 256 + threadIdx.x;
    if (idx >= 1536 * EPITCH) return;
    int r = idx / EPITCH, pos = idx % EPITCH;
    int g = pos >> 3, wi = pos & 7, q = wi >> 1, h = wi & 1;
    int kw = g * 8 + q + 4 * h;
    uint32_t v = 0;
    if (kw < 384) {
        float2 e = *reinterpret_cast<const float2*>(E + (size_t)r * 768 + 2 * kw);
        v = packbf(e.x, e.y);
    }
    g_Ebf[idx] = v;
}

// ---------------- prep: weights ----------------
#define WAB_N (12 * 320 * 72)
#define W1CP_N (6 * W1C_CHUNK_W)
__global__ void kprep_w(const float* __restrict__ W1, const float* __restrict__ W2) {
    int idx = blockIdx.x * 256 + threadIdx.x;
    if (idx < WAB_N) {
        int c = idx / (320 * 72), rem = idx % (320 * 72);
        int n = rem / 72, kk = rem % 72;
        float v = 0.f;
        if (kk < 64) {
            int kg = c * 64 + kk;
            if (n < 160) { if (n < HH) v = W1[(size_t)kg * HH + n]; }
            else { int h = n - 160; if (h < HH) v = W1[(size_t)(768 + kg) * HH + h]; }
        }
        g_wabT[idx] = __float2bfloat16(v);
    } else if (idx < WAB_N + W1CP_N + W2_W) {
        int t = idx - WAB_N;
        bool isW2 = (t >= W1CP_N);
        int c = 0, r;
        if (isW2) r = t - W1CP_N;
        else { c = t / W1C_CHUNK_W; r = t % W1C_CHUNK_W; }
        int ks = r / PKS, r1 = r % PKS;
        int lane = r1 / 44, r2 = r1 % 44;
        uint32_t v = 0;
        if (r2 < 40) {
            int nh = r2 / 20, r3 = r2 % 20, m = r3 / 4, e = r3 % 4;
            int gq = lane >> 2, qq = lane & 3;
            int nb = nh * 10 + 2 * m + (e >> 1);
            int kwl = ks * 8 + qq + (e & 1) * 4;
            int n = nb * 8 + gq;
            float v0 = 0.f, v1 = 0.f;
            if (n < HH) {
                if (isW2) {
                    int k0 = 2 * kwl;
                    if (k0 < HH)     v0 = W2[(size_t)k0 * HH + n];
                    if (k0 + 1 < HH) v1 = W2[(size_t)(k0 + 1) * HH + n];
                } else {
                    int k0 = c * 128 + 2 * kwl;
                    v0 = W1[(size_t)(1536 + k0) * HH + n];
                    v1 = W1[(size_t)(1536 + k0 + 1) * HH + n];
                }
            }
            v = packbf(v0, v1);
        }
        if (isW2) g_w2P[r] = v; else g_w1cP[(size_t)c * W1C_CHUNK_W + r] = v;
    }
}

// ---------------- k1: seeds GEMM -> g_A,g_B (pitch 152) ----------------
#define K1_E_BYTES (32 * EPITCH * 4)
#define K1_W_BYTES (320 * WABPITCH * 4)
#define K1_BAR_OFF (K1_E_BYTES + 2 * K1_W_BYTES)
#define K1_SMEM    (K1_BAR_OFF + 64)

__global__ __launch_bounds__(256, 1)
void k1_mma(const float* __restrict__ b1) {
    extern __shared__ __align__(128) char smem[];
    uint32_t* sE = (uint32_t*)smem;
    uint32_t* sW[2] = { (uint32_t*)(smem + K1_E_BYTES),
                        (uint32_t*)(smem + K1_E_BYTES + K1_W_BYTES) };
    const uint32_t barE = smem_u32(smem + K1_BAR_OFF);
    const uint32_t barW[2] = { barE + 8, barE + 16 };
    const int tid = threadIdx.x, w = tid >> 5, lane = tid & 31;
    const int gq = lane >> 2, qq = lane & 3;
    const int r0 = blockIdx.x * 32;

    if (tid == 0) {
        MBAR_INIT(barE, 1); MBAR_INIT(barW[0], 1); MBAR_INIT(barW[1], 1);
        FENCE_ASYNC();
        MBAR_EXPECT_TX(barE, K1_E_BYTES);
        bulk_g2s(smem_u32(sE), g_Ebf + (size_t)r0 * EPITCH, K1_E_BYTES, barE);
        MBAR_EXPECT_TX(barW[0], K1_W_BYTES);
        bulk_g2s(smem_u32(sW[0]), g_wabT, K1_W_BYTES, barW[0]);
        MBAR_EXPECT_TX(barW[1], K1_W_BYTES);
        bulk_g2s(smem_u32(sW[1]), g_wabT + (size_t)320 * 72, K1_W_BYTES, barW[1]);
    }
    __syncthreads();
    MBAR_WAIT(barE, 0);

    float acc[2][5][4];
#pragma unroll
    for (int t = 0; t < 2; t++)
#pragma unroll
        for (int l = 0; l < 5; l++)
#pragma unroll
            for (int u = 0; u < 4; u++) acc[t][l][u] = 0.f;

    const uint32_t* e0p = sE + (size_t)gq * EPITCH;
    const uint32_t* e1p = e0p + 8 * EPITCH;
    const uint32_t* e2p = e0p + 16 * EPITCH;
    const uint32_t* e3p = e0p + 24 * EPITCH;

    for (int c = 0; c < 12; c++) {
        MBAR_WAIT(barW[c & 1], (c >> 1) & 1);
        const uint32_t* Wb = sW[c & 1];
#pragma unroll
        for (int ks = 0; ks < 4; ks++) {
            int kb = c * 32 + ks * 8 + 2 * qq;
            uint2 e0 = *(const uint2*)(e0p + kb);
            uint2 e1 = *(const uint2*)(e1p + kb);
            uint2 e2 = *(const uint2*)(e2p + kb);
            uint2 e3 = *(const uint2*)(e3p + kb);
            uint32_t a0[4] = { e0.x, e1.x, e0.y, e1.y };
            uint32_t a1[4] = { e2.x, e3.x, e2.y, e3.y };
#pragma unroll
            for (int l = 0; l < 5; l++) {
                int nrow = (w * 5 + l) * 8 + gq;
                uint32_t b[2] = { Wb[nrow * WABPITCH + ks * 8 + qq],
                                  Wb[nrow * WABPITCH + ks * 8 + qq + 4] };
                mma16816(acc[0][l], a0, b, acc[0][l]);
                mma16816(acc[1][l], a1, b, acc[1][l]);
            }
        }
        __syncthreads();
        if (tid == 0 && c + 2 < 12) {
            MBAR_EXPECT_TX(barW[c & 1], K1_W_BYTES);
            bulk_g2s(smem_u32(sW[c & 1]), g_wabT + (size_t)(c + 2) * 320 * 72,
                     K1_W_BYTES, barW[c & 1]);
        }
    }

#pragma unroll
    for (int t = 0; t < 2; t++)
#pragma unroll
        for (int l = 0; l < 5; l++) {
            int n0 = (w * 5 + l) * 8 + 2 * qq;
            int ra = r0 + 16 * t + gq, rb = ra + 8;
#pragma unroll
            for (int u = 0; u < 4; u++) {
                int row = (u < 2) ? ra : rb;
                int n = n0 + (u & 1);
                float v = acc[t][l][u];
                if (n < 160) { if (n < HH) g_A[(size_t)row * APITCH + n] = v + __ldg(b1 + n); }
                else { int h = n - 160; if (h < HH) g_B[(size_t)row * APITCH + h] = v; }
            }
        }
}

// ---------------- k2: fused pair MLP, 2 CTAs/SM ----------------
// Compact grid (208, 8). 192 thr = 6 warps: mh=w>>1 (0..2, m32), nh=w&1 (n80 half).
// Tile: TI=12 i-rows x TJ=8 j-rows = 96 pairs.
#define K2_EI_OFF   0                                  // 12*392*4 = 18816
#define K2_EJ_OFF   18816                              // 8*392*4  = 12544
#define K2_W_OFF    31360                              // 2 x 22528 = 45056
#define K2_WBUF_B   22528                              // 4 ks per buffer
#define K2_H1_OFF   76416                              // 96*88*4 = 33792
#define K2_SC_OFF   110208                             // 96*4 = 384
#define K2_BW_OFF   110592                             // b2|W3: 1216
#define K2_BAR_OFF  111808
#define K2_SMEM     (K2_BAR_OFF + 64)                  // 111872

__global__ __launch_bounds__(192, 2)
void k2_mma(const float* __restrict__ b2,
            const float* __restrict__ W3,
            const float* __restrict__ b3) {
    const int bz = blockIdx.y;
    const int x = blockIdx.x;
    const int cumt[16] = {0,2,5,10,16,24,33,44,56,70,85,102,120,140,161,184};
    int ti = 0;
#pragma unroll
    for (int t = 1; t < 16; t++)
        if (cumt[t] <= x) ti = t;
    const int tj = x - cumt[ti];

    extern __shared__ __align__(128) char smem[];
    uint32_t* sEi = (uint32_t*)(smem + K2_EI_OFF);
    uint32_t* sEj = (uint32_t*)(smem + K2_EJ_OFF);
    uint32_t* sW[2] = { (uint32_t*)(smem + K2_W_OFF),
                        (uint32_t*)(smem + K2_W_OFF + K2_WBUF_B) };
    uint32_t* sH1 = (uint32_t*)(smem + K2_H1_OFF);
    float*    sSc = (float*)(smem + K2_SC_OFF);
    float*    sB2 = (float*)(smem + K2_BW_OFF);
    float*    sW3 = sB2 + 152;
    const uint32_t barE = smem_u32(smem + K2_BAR_OFF);
    const uint32_t barW[2] = { barE + 8, barE + 16 };
    const uint32_t barC[2] = { barE + 24, barE + 32 };
    const int tid = threadIdx.x, w = tid >> 5, lane = tid & 31;
    const int mh = w >> 1, nh = w & 1;
    const int gq = lane >> 2, qq = lane & 3;

    if (tid == 0) {
        MBAR_INIT(barE, 1); MBAR_INIT(barW[0], 1); MBAR_INIT(barW[1], 1);
        MBAR_INIT(barC[0], 6); MBAR_INIT(barC[1], 6);
        FENCE_ASYNC();
        MBAR_EXPECT_TX(barE, (12 + 8) * EPITCH * 4);
        bulk_g2s(smem_u32(sEi), g_Ebf + ((size_t)bz * 192 + ti * 12) * EPITCH, 12 * EPITCH * 4, barE);
        bulk_g2s(smem_u32(sEj), g_Ebf + ((size_t)bz * 192 + tj * 8) * EPITCH, 8 * EPITCH * 4, barE);
        MBAR_EXPECT_TX(barW[0], K2_WBUF_B);
        bulk_g2s(smem_u32(sW[0]), g_w1cP, K2_WBUF_B, barW[0]);
        MBAR_EXPECT_TX(barW[1], K2_WBUF_B);
        bulk_g2s(smem_u32(sW[1]), g_w1cP + (size_t)4 * PKS, K2_WBUF_B, barW[1]);
    }
    // stage b2/W3 (tiny)
    for (int idx = tid; idx < 304; idx += 192) {
        if (idx < 152) sB2[idx] = (idx < HH) ? b2[idx] : 0.f;
        else { int h = idx - 152; sW3[h] = (h < HH) ? W3[h] : 0.f; }
    }
    __syncthreads();
    MBAR_WAIT(barE, 0);

    float acc[2][10][4];
#pragma unroll
    for (int t = 0; t < 2; t++)
#pragma unroll
        for (int l = 0; l < 10; l++)
#pragma unroll
            for (int u = 0; u < 4; u++) acc[t][l][u] = 0.f;

    const uint32_t* eI0 = sEi + (size_t)(4 * mh + 0) * EPITCH;
    const uint32_t* eI1 = sEi + (size_t)(4 * mh + 1) * EPITCH;
    const uint32_t* eI2 = sEi + (size_t)(4 * mh + 2) * EPITCH;
    const uint32_t* eI3 = sEi + (size_t)(4 * mh + 3) * EPITCH;
    const uint32_t* eJp = sEj + (size_t)gq * EPITCH;
    const int bw_off = lane * 44 + nh * 20;

    // ---- layer 1: 12 K-chunks of 64, decoupled producer/consumer ----
    int wp0 = 0, wp1 = 0;      // full-bar phases
    int cp0 = 0, cp1 = 0;      // consumed-bar phases (issuer only)
    for (int c = 0; c < 12; c++) {
        const int buf = c & 1;
        if (buf == 0) { MBAR_WAIT(barW[0], wp0 & 1); wp0++; }
        else          { MBAR_WAIT(barW[1], wp1 & 1); wp1++; }
        const uint32_t* Wb = sW[buf];
#pragma unroll
        for (int ks = 0; ks < 4; ks++) {
            int kb = c * 32 + ks * 8 + 2 * qq;
            uint2 ej = *(const uint2*)(eJp + kb);
            uint2 e0 = *(const uint2*)(eI0 + kb);
            uint2 e1 = *(const uint2*)(eI1 + kb);
            uint2 e2 = *(const uint2*)(eI2 + kb);
            uint2 e3 = *(const uint2*)(eI3 + kb);
            uint32_t a0[4] = { bmul2(e0.x, ej.x), bmul2(e1.x, ej.x),
                               bmul2(e0.y, ej.y), bmul2(e1.y, ej.y) };
            uint32_t a1[4] = { bmul2(e2.x, ej.x), bmul2(e3.x, ej.x),
                               bmul2(e2.y, ej.y), bmul2(e3.y, ej.y) };
            const uint32_t* bp = Wb + ks * PKS + bw_off;
#pragma unroll
            for (int m = 0; m < 5; m++) {
                uint4 bb = *(const uint4*)(bp + m * 4);
                uint32_t b0[2] = { bb.x, bb.y };
                uint32_t b1r[2] = { bb.z, bb.w };
                mma16816(acc[0][2 * m],     a0, b0,  acc[0][2 * m]);
                mma16816(acc[1][2 * m],     a1, b0,  acc[1][2 * m]);
                mma16816(acc[0][2 * m + 1], a0, b1r, acc[0][2 * m + 1]);
                mma16816(acc[1][2 * m + 1], a1, b1r, acc[1][2 * m + 1]);
            }
        }
        __syncwarp();
        if (lane == 0) MBAR_ARRIVE(barC[buf]);
        if (w == 0 && lane == 0) {
            if (buf == 0) { MBAR_WAIT(barC[0], cp0 & 1); cp0++; }
            else          { MBAR_WAIT(barC[1], cp1 & 1); cp1++; }
            if (c + 2 < 12) {
                MBAR_EXPECT_TX(barW[buf], K2_WBUF_B);
                bulk_g2s(smem_u32(sW[buf]), g_w1cP + (size_t)(c + 2) * 4 * PKS,
                         K2_WBUF_B, barW[buf]);
            } else if (c == 10) {   // buf0 free -> W2 ks0-3
                MBAR_EXPECT_TX(barW[0], K2_WBUF_B);
                bulk_g2s(smem_u32(sW[0]), g_w2P, K2_WBUF_B, barW[0]);
            } else {                // c == 11, buf1 free -> W2 ks4-7
                MBAR_EXPECT_TX(barW[1], K2_WBUF_B);
                bulk_g2s(smem_u32(sW[1]), g_w2P + (size_t)4 * PKS, K2_WBUF_B, barW[1]);
            }
        }
    }

    // ---- epilogue 1: + seeds (L2 gmem), ReLU, bf16 -> sH1 ----
    const float* Bj = g_B + ((size_t)bz * 192 + tj * 8 + gq) * APITCH;
#pragma unroll
    for (int t = 0; t < 2; t++) {
        const float* A0 = g_A + ((size_t)bz * 192 + ti * 12 + 4 * mh + 2 * t) * APITCH;
        const float* A1 = A0 + APITCH;
#pragma unroll
        for (int l = 0; l < 10; l++) {
            int nbg = nh * 10 + l;
            int h0 = nbg * 8 + 2 * qq;
            float v0 = 0.f, v1 = 0.f, v2 = 0.f, v3 = 0.f;
            if (h0 < HH) {
                float2 a0v = *(const float2*)(A0 + h0);
                float2 a1v = *(const float2*)(A1 + h0);
                float2 bjv = *(const float2*)(Bj + h0);
                v0 = fmaxf(acc[t][l][0] + a0v.x + bjv.x, 0.f);
                v1 = fmaxf(acc[t][l][1] + a0v.y + bjv.y, 0.f);
                v2 = fmaxf(acc[t][l][2] + a1v.x + bjv.x, 0.f);
                v3 = fmaxf(acc[t][l][3] + a1v.y + bjv.y, 0.f);
            }
            int kw = nbg * 4 + qq;
            int ilvw = ((kw >> 3) << 3) + 2 * (kw & 3) + ((kw >> 2) & 1);
            sH1[(32 * mh + 16 * t + gq) * H1PITCH + ilvw]     = packbf(v0, v1);
            sH1[(32 * mh + 16 * t + 8 + gq) * H1PITCH + ilvw] = packbf(v2, v3);
        }
    }
    NBAR(1 + mh, 64);          // nh-pair exchange of h1 halves

    // ---- layer 2: K=160 as 3 slabs (4+4+2 ks) through the 2 buffers ----
    float ac2[2][10][4];
#pragma unroll
    for (int t = 0; t < 2; t++)
#pragma unroll
        for (int l = 0; l < 10; l++)
#pragma unroll
            for (int u = 0; u < 4; u++) ac2[t][l][u] = 0.f;

    const uint32_t* h0p = sH1 + (size_t)(32 * mh + gq) * H1PITCH;
    const uint32_t* h1p = h0p + 8 * H1PITCH;
    const uint32_t* h2p = h0p + 16 * H1PITCH;
    const uint32_t* h3p = h0p + 24 * H1PITCH;

#define L2_STEP(Wb, ks, s) do { \
        int kb = (ks) * 8 + 2 * qq; \
        uint2 x0 = *(const uint2*)(h0p + kb); \
        uint2 x1 = *(const uint2*)(h1p + kb); \
        uint2 x2 = *(const uint2*)(h2p + kb); \
        uint2 x3 = *(const uint2*)(h3p + kb); \
        uint32_t a0[4] = { x0.x, x1.x, x0.y, x1.y }; \
        uint32_t a1[4] = { x2.x, x3.x, x2.y, x3.y }; \
        const uint32_t* bp = (Wb) + (s) * PKS + bw_off; \
        _Pragma("unroll") \
        for (int m = 0; m < 5; m++) { \
            uint4 bb = *(const uint4*)(bp + m * 4); \
            uint32_t b0[2] = { bb.x, bb.y }; \
            uint32_t b1r[2] = { bb.z, bb.w }; \
            mma16816(ac2[0][2 * m],     a0, b0,  ac2[0][2 * m]); \
            mma16816(ac2[1][2 * m],     a1, b0,  ac2[1][2 * m]); \
            mma16816(ac2[0][2 * m + 1], a0, b1r, ac2[0][2 * m + 1]); \
            mma16816(ac2[1][2 * m + 1], a1, b1r, ac2[1][2 * m + 1]); \
        } \
    } while (0)

    MBAR_WAIT(barW[0], wp0 & 1); wp0++;    // W2 ks0-3
#pragma unroll
    for (int s = 0; s < 4; s++) L2_STEP(sW[0], s, s);
    __syncwarp();
    if (lane == 0) MBAR_ARRIVE(barC[0]);
    if (w == 0 && lane == 0) {             // refill buf0 with W2 ks8-9
        MBAR_WAIT(barC[0], cp0 & 1); cp0++;
        MBAR_EXPECT_TX(barW[0], 2 * PKS * 4);
        bulk_g2s(smem_u32(sW[0]), g_w2P + (size_t)8 * PKS, 2 * PKS * 4, barW[0]);
    }
    MBAR_WAIT(barW[1], wp1 & 1); wp1++;    // W2 ks4-7
#pragma unroll
    for (int s = 0; s < 4; s++) L2_STEP(sW[1], 4 + s, s);
    MBAR_WAIT(barW[0], wp0 & 1); wp0++;    // W2 ks8-9
#pragma unroll
    for (int s = 0; s < 2; s++) L2_STEP(sW[0], 8 + s, s);

    // ---- epilogue 2: +b2, ReLU, dot W3 (smem); nh-pair exchange via sSc ----
    float sp[2][2] = { {0.f, 0.f}, {0.f, 0.f} };
#pragma unroll
    for (int t = 0; t < 2; t++)
#pragma unroll
        for (int l = 0; l < 10; l++) {
            int h0 = (nh * 10 + l) * 8 + 2 * qq;
            if (h0 < HH) {
                float2 bv = *(const float2*)(sB2 + h0);
                float2 wv = *(const float2*)(sW3 + h0);
                sp[t][0] += fmaxf(ac2[t][l][0] + bv.x, 0.f) * wv.x
                          + fmaxf(ac2[t][l][1] + bv.y, 0.f) * wv.y;
                sp[t][1] += fmaxf(ac2[t][l][2] + bv.x, 0.f) * wv.x
                          + fmaxf(ac2[t][l][3] + bv.y, 0.f) * wv.y;
            }
        }
#pragma unroll
    for (int t = 0; t < 2; t++)
#pragma unroll
        for (int s = 0; s < 2; s++) {
            sp[t][s] += __shfl_xor_sync(0xffffffffu, sp[t][s], 1);
            sp[t][s] += __shfl_xor_sync(0xffffffffu, sp[t][s], 2);
        }
    if (nh == 0 && qq == 0) {
#pragma unroll
        for (int t = 0; t < 2; t++)
#pragma unroll
            for (int s = 0; s < 2; s++)
                sSc[32 * mh + 16 * t + 8 * s + gq] = sp[t][s];
    }
    NBAR(8 + mh, 64);
    if (nh == 1 && qq == 0) {
        float b3v = __ldg(b3);
#pragma unroll
        for (int t = 0; t < 2; t++)
#pragma unroll
            for (int s = 0; s < 2; s++) {
                int r = 32 * mh + 16 * t + 8 * s + gq;
                int ip = ti * 12 + (r >> 3), jp = tj * 8 + (r & 7);
                if (jp < ip)
                    g_S[((size_t)bz * 192 + ip) * 192 + jp] = sp[t][s] + sSc[r] + b3v;
            }
    }
}

// ---------------- k3: tril softmax ----------------
__global__ void k3_softmax(float* __restrict__ out) {
    const int i = blockIdx.x, b = blockIdx.y, j = threadIdx.x;
    float val;
    if (j < i)       val = g_S[((size_t)b * 192 + i) * 192 + j];
    else if (j == i) val = 0.f;
    else             val = -1e30f;

    __shared__ float red[6];
    float m = val;
#pragma unroll
    for (int o = 16; o; o >>= 1) m = fmaxf(m, __shfl_xor_sync(0xffffffffu, m, o));
    if ((j & 31) == 0) red[j >> 5] = m;
    __syncthreads();
    float M = fmaxf(fmaxf(fmaxf(red[0], red[1]), fmaxf(red[2], red[3])), fmaxf(red[4], red[5]));
    __syncthreads();
    float e = (j <= i) ? expf(val - M) : 0.f;
    float s = e;
#pragma unroll
    for (int o = 16; o; o >>= 1) s += __shfl_xor_sync(0xffffffffu, s, o);
    if ((j & 31) == 0) red[j >> 5] = s;
    __syncthreads();
    float S = red[0] + red[1] + red[2] + red[3] + red[4] + red[5];
    out[((size_t)b * 192 + i) * 192 + j] = (j <= i) ? (e / S) : -1000.0f;
}

// ---------------------------------------------------------------------------
extern "C" void kernel_launch(void* const* d_in, const int* in_sizes, int n_in,
                              void* d_out, int out_size) {
    const float* E  = (const float*)d_in[0];
    const float* W1 = (const float*)d_in[1];
    const float* b1 = (const float*)d_in[2];
    const float* W2 = (const float*)d_in[3];
    const float* b2 = (const float*)d_in[4];
    const float* W3 = (const float*)d_in[5];
    const float* b3 = (const float*)d_in[6];
    float* out = (float*)d_out;

    cudaFuncSetAttribute(k1_mma, cudaFuncAttributeMaxDynamicSharedMemorySize, K1_SMEM);
    cudaFuncSetAttribute(k2_mma, cudaFuncAttributeMaxDynamicSharedMemorySize, K2_SMEM);

    kprep_e<<<(1536 * EPITCH + 255) / 256, 256>>>(E);
    kprep_w<<<(WAB_N + W1CP_N + W2_W + 255) / 256, 256>>>(W1, W2);
    k1_mma<<<48, 256, K1_SMEM>>>(b1);
    k2_mma<<<dim3(208, 8), 192, K2_SMEM>>>(b2, W3, b3);
    k3_softmax<<<dim3(192, 8), 192>>>(out);
}

// round 9
// speedup vs baseline: 1.0879x; 1.0002x over previous
#include <cuda_runtime.h>
#include <cuda_bf16.h>
#include <cstdint>

#define HH 150
#define APITCH 152          // g_A/g_B row pitch (floats)

#define EPITCH 392          // E row pitch in u32 words
#define H1PITCH 88          // h1 row pitch in u32 words
#define WABPITCH 36         // k1 weight row pitch (u32 words)

// Packed-fragment W blob geometry: per k16-step: 32 lanes * 44 words
#define PKS 1408
#define W1C_CHUNK_W 11264   // prep-kernel layout unit; storage is ks-contiguous
#define W2_W 14080          // 10 ks (K=160)
#define SLAB_W (2 * PKS)    // 2 ks per fetch slab
#define NFETCH 29           // 24 W1c slabs + 5 W2 slabs

// ---------------- device scratch ----------------
__device__ __align__(16) uint32_t      g_Ebf[1536 * EPITCH];
__device__ __align__(16) __nv_bfloat16 g_wabT[12 * 320 * 72];
__device__ __align__(16) uint32_t      g_w1cP[6 * W1C_CHUNK_W];   // 48 ks contiguous
__device__ __align__(16) uint32_t      g_w2P[W2_W];               // 10 ks contiguous
__device__ __align__(16) float g_A[1536 * APITCH];
__device__ __align__(16) float g_B[1536 * APITCH];
__device__ float g_S[8 * 192 * 192];
__device__ float g_S2[8 * 192 * 192];

// ---------------- helpers ----------------
__device__ __forceinline__ uint32_t smem_u32(const void* p) {
    uint32_t a;
    asm("{ .reg .u64 t; cvta.to.shared.u64 t, %1; cvt.u32.u64 %0, t; }" : "=r"(a) : "l"(p));
    return a;
}
__device__ __forceinline__ uint32_t packbf(float lo, float hi) {
    uint32_t d; asm("cvt.rn.bf16x2.f32 %0, %1, %2;" : "=r"(d) : "f"(hi), "f"(lo)); return d;
}
__device__ __forceinline__ uint32_t bmul2(uint32_t a, uint32_t b) {
    uint32_t d; asm("mul.rn.bf16x2 %0, %1, %2;" : "=r"(d) : "r"(a), "r"(b)); return d;
}
__device__ __forceinline__ void mma16816(float* d, const uint32_t* a, const uint32_t* b,
                                         const float* c) {
    asm volatile(
        "mma.sync.aligned.m16n8k16.row.col.f32.bf16.bf16.f32 "
        "{%0,%1,%2,%3}, {%4,%5,%6,%7}, {%8,%9}, {%10,%11,%12,%13};"
        : "=f"(d[0]), "=f"(d[1]), "=f"(d[2]), "=f"(d[3])
        : "r"(a[0]), "r"(a[1]), "r"(a[2]), "r"(a[3]), "r"(b[0]), "r"(b[1]),
          "f"(c[0]), "f"(c[1]), "f"(c[2]), "f"(c[3]));
}
#define MBAR_INIT(mb, cnt) asm volatile("mbarrier.init.shared.b64 [%0], %1;" :: "r"((uint32_t)(mb)), "r"((uint32_t)(cnt)) : "memory")
#define MBAR_EXPECT_TX(mb, n) asm volatile("mbarrier.arrive.expect_tx.shared.b64 _, [%0], %1;" :: "r"((uint32_t)(mb)), "r"((uint32_t)(n)) : "memory")
#define MBAR_ARRIVE(mb) asm volatile("mbarrier.arrive.release.cta.shared::cta.b64 _, [%0];" :: "r"((uint32_t)(mb)) : "memory")
#define FENCE_ASYNC() asm volatile("fence.proxy.async.shared::cta;" ::: "memory")
#define NBAR(id, cnt) asm volatile("bar.sync %0, %1;" :: "r"(id), "r"(cnt) : "memory")
#define MBAR_WAIT(mb, ph) do { \
    uint32_t _m = (uint32_t)(mb); uint32_t _p = (uint32_t)(ph); uint32_t _d; \
    asm volatile("{\n\t.reg .pred p;\n\tmbarrier.try_wait.parity.acquire.cta.shared::cta.b64 p, [%1], %2;\n\tselp.b32 %0, 1, 0, p;\n\t}" \
        : "=r"(_d) : "r"(_m), "r"(_p) : "memory"); \
    if (!_d) { \
        asm volatile("{\n\t.reg .pred P1;\n\tWL_%=:\n\tmbarrier.try_wait.parity.acquire.cta.shared::cta.b64 P1, [%0], %1, 0x989680;\n\t@P1 bra.uni WD_%=;\n\tbra.uni WL_%=;\n\tWD_%=:\n\t}" \
            :: "r"(_m), "r"(_p) : "memory"); \
    } } while (0)
__device__ __forceinline__ void bulk_g2s(uint32_t dst, const void* src, uint32_t bytes, uint32_t mbar) {
    asm volatile("cp.async.bulk.shared::cta.global.mbarrier::complete_tx::bytes [%0], [%1], %2, [%3];"
        :: "r"(dst), "l"(src), "r"(bytes), "r"(mbar) : "memory");
}

// ---------------- prep: E -> interleaved bf16x2 ----------------
__global__ void kprep_e(const float* __restrict__ E) {
    int idx = blockIdx.x * 256 + threadIdx.x;
    if (idx >= 1536 * EPITCH) return;
    int r = idx / EPITCH, pos = idx % EPITCH;
    int g = pos >> 3, wi = pos & 7, q = wi >> 1, h = wi & 1;
    int kw = g * 8 + q + 4 * h;
    uint32_t v = 0;
    if (kw < 384) {
        float2 e = *reinterpret_cast<const float2*>(E + (size_t)r * 768 + 2 * kw);
        v = packbf(e.x, e.y);
    }
    g_Ebf[idx] = v;
}

// ---------------- prep: weights ----------------
#define WAB_N (12 * 320 * 72)
#define W1CP_N (6 * W1C_CHUNK_W)
__global__ void kprep_w(const float* __restrict__ W1, const float* __restrict__ W2) {
    int idx = blockIdx.x * 256 + threadIdx.x;
    if (idx < WAB_N) {
        int c = idx / (320 * 72), rem = idx % (320 * 72);
        int n = rem / 72, kk = rem % 72;
        float v = 0.f;
        if (kk < 64) {
            int kg = c * 64 + kk;
            if (n < 160) { if (n < HH) v = W1[(size_t)kg * HH + n]; }
            else { int h = n - 160; if (h < HH) v = W1[(size_t)(768 + kg) * HH + h]; }
        }
        g_wabT[idx] = __float2bfloat16(v);
    } else if (idx < WAB_N + W1CP_N + W2_W) {
        int t = idx - WAB_N;
        bool isW2 = (t >= W1CP_N);
        int c = 0, r;
        if (isW2) r = t - W1CP_N;
        else { c = t / W1C_CHUNK_W; r = t % W1C_CHUNK_W; }
        int ks = r / PKS, r1 = r % PKS;
        int lane = r1 / 44, r2 = r1 % 44;
        uint32_t v = 0;
        if (r2 < 40) {
            int nh = r2 / 20, r3 = r2 % 20, m = r3 / 4, e = r3 % 4;
            int gq = lane >> 2, qq = lane & 3;
            int nb = nh * 10 + 2 * m + (e >> 1);
            int kwl = ks * 8 + qq + (e & 1) * 4;
            int n = nb * 8 + gq;
            float v0 = 0.f, v1 = 0.f;
            if (n < HH) {
                if (isW2) {
                    int k0 = 2 * kwl;
                    if (k0 < HH)     v0 = W2[(size_t)k0 * HH + n];
                    if (k0 + 1 < HH) v1 = W2[(size_t)(k0 + 1) * HH + n];
                } else {
                    int k0 = c * 128 + 2 * kwl;
                    v0 = W1[(size_t)(1536 + k0) * HH + n];
                    v1 = W1[(size_t)(1536 + k0 + 1) * HH + n];
                }
            }
            v = packbf(v0, v1);
        }
        if (isW2) g_w2P[r] = v; else g_w1cP[(size_t)c * W1C_CHUNK_W + r] = v;
    }
}

// ---------------- k1: seeds GEMM -> g_A,g_B (pitch 152) ----------------
#define K1_E_BYTES (32 * EPITCH * 4)
#define K1_W_BYTES (320 * WABPITCH * 4)
#define K1_BAR_OFF (K1_E_BYTES + 2 * K1_W_BYTES)
#define K1_SMEM    (K1_BAR_OFF + 64)

__global__ __launch_bounds__(256, 1)
void k1_mma(const float* __restrict__ b1) {
    extern __shared__ __align__(128) char smem[];
    uint32_t* sE = (uint32_t*)smem;
    uint32_t* sW[2] = { (uint32_t*)(smem + K1_E_BYTES),
                        (uint32_t*)(smem + K1_E_BYTES + K1_W_BYTES) };
    const uint32_t barE = smem_u32(smem + K1_BAR_OFF);
    const uint32_t barW[2] = { barE + 8, barE + 16 };
    const int tid = threadIdx.x, w = tid >> 5, lane = tid & 31;
    const int gq = lane >> 2, qq = lane & 3;
    const int r0 = blockIdx.x * 32;

    if (tid == 0) {
        MBAR_INIT(barE, 1); MBAR_INIT(barW[0], 1); MBAR_INIT(barW[1], 1);
        FENCE_ASYNC();
        MBAR_EXPECT_TX(barE, K1_E_BYTES);
        bulk_g2s(smem_u32(sE), g_Ebf + (size_t)r0 * EPITCH, K1_E_BYTES, barE);
        MBAR_EXPECT_TX(barW[0], K1_W_BYTES);
        bulk_g2s(smem_u32(sW[0]), g_wabT, K1_W_BYTES, barW[0]);
        MBAR_EXPECT_TX(barW[1], K1_W_BYTES);
        bulk_g2s(smem_u32(sW[1]), g_wabT + (size_t)320 * 72, K1_W_BYTES, barW[1]);
    }
    __syncthreads();
    MBAR_WAIT(barE, 0);

    float acc[2][5][4];
#pragma unroll
    for (int t = 0; t < 2; t++)
#pragma unroll
        for (int l = 0; l < 5; l++)
#pragma unroll
            for (int u = 0; u < 4; u++) acc[t][l][u] = 0.f;

    const uint32_t* e0p = sE + (size_t)gq * EPITCH;
    const uint32_t* e1p = e0p + 8 * EPITCH;
    const uint32_t* e2p = e0p + 16 * EPITCH;
    const uint32_t* e3p = e0p + 24 * EPITCH;

    for (int c = 0; c < 12; c++) {
        MBAR_WAIT(barW[c & 1], (c >> 1) & 1);
        const uint32_t* Wb = sW[c & 1];
#pragma unroll
        for (int ks = 0; ks < 4; ks++) {
            int kb = c * 32 + ks * 8 + 2 * qq;
            uint2 e0 = *(const uint2*)(e0p + kb);
            uint2 e1 = *(const uint2*)(e1p + kb);
            uint2 e2 = *(const uint2*)(e2p + kb);
            uint2 e3 = *(const uint2*)(e3p + kb);
            uint32_t a0[4] = { e0.x, e1.x, e0.y, e1.y };
            uint32_t a1[4] = { e2.x, e3.x, e2.y, e3.y };
#pragma unroll
            for (int l = 0; l < 5; l++) {
                int nrow = (w * 5 + l) * 8 + gq;
                uint32_t b[2] = { Wb[nrow * WABPITCH + ks * 8 + qq],
                                  Wb[nrow * WABPITCH + ks * 8 + qq + 4] };
                mma16816(acc[0][l], a0, b, acc[0][l]);
                mma16816(acc[1][l], a1, b, acc[1][l]);
            }
        }
        __syncthreads();
        if (tid == 0 && c + 2 < 12) {
            MBAR_EXPECT_TX(barW[c & 1], K1_W_BYTES);
            bulk_g2s(smem_u32(sW[c & 1]), g_wabT + (size_t)(c + 2) * 320 * 72,
                     K1_W_BYTES, barW[c & 1]);
        }
    }

#pragma unroll
    for (int t = 0; t < 2; t++)
#pragma unroll
        for (int l = 0; l < 5; l++) {
            int n0 = (w * 5 + l) * 8 + 2 * qq;
            int ra = r0 + 16 * t + gq, rb = ra + 8;
#pragma unroll
            for (int u = 0; u < 4; u++) {
                int row = (u < 2) ? ra : rb;
                int n = n0 + (u & 1);
                float v = acc[t][l][u];
                if (n < 160) { if (n < HH) g_A[(size_t)row * APITCH + n] = v + __ldg(b1 + n); }
                else { int h = n - 160; if (h < HH) g_B[(size_t)row * APITCH + h] = v; }
            }
        }
}

// ---------------- k2: fused pair MLP, 2 CTAs/SM, 4-deep W ring ----------------
// Compact grid (208, 8). 192 thr = 6 warps: mh=w>>1 (0..2, m32), nh=w&1 (n80 half).
#define K2_EI_OFF   0                                  // 12*392*4 = 18816
#define K2_EJ_OFF   18816                              // 8*392*4  = 12544
#define K2_W_OFF    31360                              // 4 x 11264 = 45056
#define K2_WBUF_B   (SLAB_W * 4)                       // 11264 per buffer
#define K2_H1_OFF   76416                              // 96*88*4 = 33792
#define K2_BW_OFF   110208                             // b2|W3: 1216
#define K2_BAR_OFF  111424
#define K2_SMEM     (K2_BAR_OFF + 128)                 // 111552

__global__ __launch_bounds__(192, 2)
void k2_mma(const float* __restrict__ b2,
            const float* __restrict__ W3) {
    const int bz = blockIdx.y;
    const int x = blockIdx.x;
    const int cumt[16] = {0,2,5,10,16,24,33,44,56,70,85,102,120,140,161,184};
    int ti = 0;
#pragma unroll
    for (int t = 1; t < 16; t++)
        if (cumt[t] <= x) ti = t;
    const int tj = x - cumt[ti];

    extern __shared__ __align__(128) char smem[];
    uint32_t* sEi = (uint32_t*)(smem + K2_EI_OFF);
    uint32_t* sEj = (uint32_t*)(smem + K2_EJ_OFF);
    uint32_t* sWr = (uint32_t*)(smem + K2_W_OFF);      // ring: 4 x SLAB_W
    uint32_t* sH1 = (uint32_t*)(smem + K2_H1_OFF);
    float*    sB2 = (float*)(smem + K2_BW_OFF);
    float*    sW3 = sB2 + 152;
    const uint32_t barE = smem_u32(smem + K2_BAR_OFF);
    const uint32_t barW0 = barE + 8;    // barW[b] = barW0 + 8b
    const uint32_t barC0 = barE + 40;   // barC[b] = barC0 + 8b
    const int tid = threadIdx.x, w = tid >> 5, lane = tid & 31;
    const int mh = w >> 1, nh = w & 1;
    const int gq = lane >> 2, qq = lane & 3;

    if (tid == 0) {
        MBAR_INIT(barE, 1);
#pragma unroll
        for (int b = 0; b < 4; b++) { MBAR_INIT(barW0 + 8 * b, 1); MBAR_INIT(barC0 + 8 * b, 6); }
        FENCE_ASYNC();
        MBAR_EXPECT_TX(barE, (12 + 8) * EPITCH * 4);
        bulk_g2s(smem_u32(sEi), g_Ebf + ((size_t)bz * 192 + ti * 12) * EPITCH, 12 * EPITCH * 4, barE);
        bulk_g2s(smem_u32(sEj), g_Ebf + ((size_t)bz * 192 + tj * 8) * EPITCH, 8 * EPITCH * 4, barE);
#pragma unroll
        for (int f = 0; f < 4; f++) {
            MBAR_EXPECT_TX(barW0 + 8 * f, SLAB_W * 4);
            bulk_g2s(smem_u32(sWr + f * SLAB_W), g_w1cP + (size_t)f * SLAB_W, SLAB_W * 4, barW0 + 8 * f);
        }
    }
    // stage b2/W3; zero sH1 pad words kw 76..79 (read by L2 ks9 against zero weights)
    for (int idx = tid; idx < 304; idx += 192) {
        if (idx < 152) sB2[idx] = (idx < HH) ? b2[idx] : 0.f;
        else { int h = idx - 152; sW3[h] = (h < HH) ? W3[h] : 0.f; }
    }
    for (int idx = tid; idx < 96 * 4; idx += 192)
        sH1[(idx >> 2) * H1PITCH + 76 + (idx & 3)] = 0;
    __syncthreads();
    MBAR_WAIT(barE, 0);

    float acc[2][10][4];
#pragma unroll
    for (int t = 0; t < 2; t++)
#pragma unroll
        for (int l = 0; l < 10; l++)
#pragma unroll
            for (int u = 0; u < 4; u++) acc[t][l][u] = 0.f;

    const uint32_t* eI0 = sEi + (size_t)(4 * mh + 0) * EPITCH;
    const uint32_t* eI1 = sEi + (size_t)(4 * mh + 1) * EPITCH;
    const uint32_t* eI2 = sEi + (size_t)(4 * mh + 2) * EPITCH;
    const uint32_t* eI3 = sEi + (size_t)(4 * mh + 3) * EPITCH;
    const uint32_t* eJp = sEj + (size_t)gq * EPITCH;
    const int bw_off = lane * 44 + nh * 20;
    const bool full_n = (nh == 0);   // nh==1 skips all-zero n-block 19 (n 152..159)

    // inner MMA step macro: A fragments given, B from bp; skips dead n-block for nh==1
#define MMA_NBLOCKS(ACC, a0, a1, bp) do { \
        _Pragma("unroll") \
        for (int m = 0; m < 4; m++) { \
            uint4 bb = *(const uint4*)((bp) + m * 4); \
            uint32_t b0[2] = { bb.x, bb.y }; \
            uint32_t b1r[2] = { bb.z, bb.w }; \
            mma16816(ACC[0][2 * m],     a0, b0,  ACC[0][2 * m]); \
            mma16816(ACC[1][2 * m],     a1, b0,  ACC[1][2 * m]); \
            mma16816(ACC[0][2 * m + 1], a0, b1r, ACC[0][2 * m + 1]); \
            mma16816(ACC[1][2 * m + 1], a1, b1r, ACC[1][2 * m + 1]); \
        } \
        { \
            uint4 bb = *(const uint4*)((bp) + 16); \
            uint32_t b0[2] = { bb.x, bb.y }; \
            mma16816(ACC[0][8], a0, b0, ACC[0][8]); \
            mma16816(ACC[1][8], a1, b0, ACC[1][8]); \
            if (full_n) { \
                uint32_t b1r[2] = { bb.z, bb.w }; \
                mma16816(ACC[0][9], a0, b1r, ACC[0][9]); \
                mma16816(ACC[1][9], a1, b1r, ACC[1][9]); \
            } \
        } \
    } while (0)

    // ---- layer 1: 24 slabs of 2 k16-steps through the 4-buffer ring ----
    for (int f = 0; f < 24; f++) {
        const int buf = f & 3;
        const uint32_t bw = barW0 + 8 * buf, bc = barC0 + 8 * buf;
        MBAR_WAIT(bw, (f >> 2) & 1);
        const uint32_t* Wb = sWr + buf * SLAB_W;
#pragma unroll
        for (int ks = 0; ks < 2; ks++) {
            int kb = f * 16 + ks * 8 + 2 * qq;
            uint2 ej = *(const uint2*)(eJp + kb);
            uint2 e0 = *(const uint2*)(eI0 + kb);
            uint2 e1 = *(const uint2*)(eI1 + kb);
            uint2 e2 = *(const uint2*)(eI2 + kb);
            uint2 e3 = *(const uint2*)(eI3 + kb);
            uint32_t a0[4] = { bmul2(e0.x, ej.x), bmul2(e1.x, ej.x),
                               bmul2(e0.y, ej.y), bmul2(e1.y, ej.y) };
            uint32_t a1[4] = { bmul2(e2.x, ej.x), bmul2(e3.x, ej.x),
                               bmul2(e2.y, ej.y), bmul2(e3.y, ej.y) };
            const uint32_t* bp = Wb + ks * PKS + bw_off;
            MMA_NBLOCKS(acc, a0, a1, bp);
        }
        __syncwarp();
        if (lane == 0) MBAR_ARRIVE(bc);
        if (w == 0 && lane == 0) {
            MBAR_WAIT(bc, (f >> 2) & 1);
            int nf = f + 4;
            const uint32_t* src = (nf < 24) ? g_w1cP + (size_t)nf * SLAB_W
                                            : g_w2P + (size_t)(nf - 24) * SLAB_W;
            MBAR_EXPECT_TX(bw, SLAB_W * 4);
            bulk_g2s(smem_u32(sWr + buf * SLAB_W), src, SLAB_W * 4, bw);
        }
    }

    // ---- epilogue 1: + seeds (L2 gmem), ReLU, bf16 -> sH1 ----
    const float* Bj = g_B + ((size_t)bz * 192 + tj * 8 + gq) * APITCH;
#pragma unroll
    for (int t = 0; t < 2; t++) {
        const float* A0 = g_A + ((size_t)bz * 192 + ti * 12 + 4 * mh + 2 * t) * APITCH;
        const float* A1 = A0 + APITCH;
#pragma unroll
        for (int l = 0; l < 10; l++) {
            if (l == 9 && !full_n) break;    // dead n-block; pad words pre-zeroed
            int nbg = nh * 10 + l;
            int h0 = nbg * 8 + 2 * qq;
            float v0 = 0.f, v1 = 0.f, v2 = 0.f, v3 = 0.f;
            if (h0 < HH) {
                float2 a0v = *(const float2*)(A0 + h0);
                float2 a1v = *(const float2*)(A1 + h0);
                float2 bjv = *(const float2*)(Bj + h0);
                v0 = fmaxf(acc[t][l][0] + a0v.x + bjv.x, 0.f);
                v1 = fmaxf(acc[t][l][1] + a0v.y + bjv.y, 0.f);
                v2 = fmaxf(acc[t][l][2] + a1v.x + bjv.x, 0.f);
                v3 = fmaxf(acc[t][l][3] + a1v.y + bjv.y, 0.f);
            }
            int kw = nbg * 4 + qq;
            int ilvw = ((kw >> 3) << 3) + 2 * (kw & 3) + ((kw >> 2) & 1);
            sH1[(32 * mh + 16 * t + gq) * H1PITCH + ilvw]     = packbf(v0, v1);
            sH1[(32 * mh + 16 * t + 8 + gq) * H1PITCH + ilvw] = packbf(v2, v3);
        }
    }
    NBAR(1 + mh, 64);          // nh-pair exchange of h1 halves

    // ---- layer 2: K=160 = fetch slots f=24..28 (2 ks each) ----
    float ac2[2][10][4];
#pragma unroll
    for (int t = 0; t < 2; t++)
#pragma unroll
        for (int l = 0; l < 10; l++)
#pragma unroll
            for (int u = 0; u < 4; u++) ac2[t][l][u] = 0.f;

    const uint32_t* h0p = sH1 + (size_t)(32 * mh + gq) * H1PITCH;
    const uint32_t* h1p = h0p + 8 * H1PITCH;
    const uint32_t* h2p = h0p + 16 * H1PITCH;
    const uint32_t* h3p = h0p + 24 * H1PITCH;

#pragma unroll
    for (int f = 24; f < 29; f++) {
        const int buf = f & 3;
        const uint32_t bw = barW0 + 8 * buf, bc = barC0 + 8 * buf;
        MBAR_WAIT(bw, (f >> 2) & 1);
        const uint32_t* Wb = sWr + buf * SLAB_W;
#pragma unroll
        for (int ks2 = 0; ks2 < 2; ks2++) {
            int kb = (f - 24) * 16 + ks2 * 8 + 2 * qq;
            uint2 x0 = *(const uint2*)(h0p + kb);
            uint2 x1 = *(const uint2*)(h1p + kb);
            uint2 x2 = *(const uint2*)(h2p + kb);
            uint2 x3 = *(const uint2*)(h3p + kb);
            uint32_t a0[4] = { x0.x, x1.x, x0.y, x1.y };
            uint32_t a1[4] = { x2.x, x3.x, x2.y, x3.y };
            const uint32_t* bp = Wb + ks2 * PKS + bw_off;
            MMA_NBLOCKS(ac2, a0, a1, bp);
        }
        if (f == 24) {   // refill f=28 (W2 ks 8-9) into buf0 once all warps consumed f=24
            __syncwarp();
            if (lane == 0) MBAR_ARRIVE(bc);
            if (w == 0 && lane == 0) {
                MBAR_WAIT(bc, (f >> 2) & 1);
                MBAR_EXPECT_TX(bw, SLAB_W * 4);
                bulk_g2s(smem_u32(sWr + buf * SLAB_W), g_w2P + (size_t)4 * SLAB_W,
                         SLAB_W * 4, bw);
            }
        }
    }

    // ---- epilogue 2: +b2, ReLU, dot W3; partials to g_S / g_S2 (no exchange) ----
    float sp[2][2] = { {0.f, 0.f}, {0.f, 0.f} };
#pragma unroll
    for (int t = 0; t < 2; t++)
#pragma unroll
        for (int l = 0; l < 10; l++) {
            if (l == 9 && !full_n) break;
            int h0 = (nh * 10 + l) * 8 + 2 * qq;
            if (h0 < HH) {
                float2 bv = *(const float2*)(sB2 + h0);
                float2 wv = *(const float2*)(sW3 + h0);
                sp[t][0] += fmaxf(ac2[t][l][0] + bv.x, 0.f) * wv.x
                          + fmaxf(ac2[t][l][1] + bv.y, 0.f) * wv.y;
                sp[t][1] += fmaxf(ac2[t][l][2] + bv.x, 0.f) * wv.x
                          + fmaxf(ac2[t][l][3] + bv.y, 0.f) * wv.y;
            }
        }
#pragma unroll
    for (int t = 0; t < 2; t++)
#pragma unroll
        for (int s = 0; s < 2; s++) {
            sp[t][s] += __shfl_xor_sync(0xffffffffu, sp[t][s], 1);
            sp[t][s] += __shfl_xor_sync(0xffffffffu, sp[t][s], 2);
        }
    if (qq == 0) {
        float* dst = full_n ? g_S2 : g_S;
#pragma unroll
        for (int t = 0; t < 2; t++)
#pragma unroll
            for (int s = 0; s < 2; s++) {
                int r = 32 * mh + 16 * t + 8 * s + gq;
                int ip = ti * 12 + (r >> 3), jp = tj * 8 + (r & 7);
                if (jp < ip)
                    dst[((size_t)bz * 192 + ip) * 192 + jp] = sp[t][s];
            }
    }
}

// ---------------- k3: tril softmax (sums the two partial-score arrays) ----------------
__global__ void k3_softmax(float* __restrict__ out, const float* __restrict__ b3) {
    const int i = blockIdx.x, b = blockIdx.y, j = threadIdx.x;
    const float b3v = __ldg(b3);
    float val;
    if (j < i) {
        size_t idx = ((size_t)b * 192 + i) * 192 + j;
        val = g_S[idx] + g_S2[idx] + b3v;
    } else if (j == i) val = 0.f;
    else               val = -1e30f;

    __shared__ float red[6];
    float m = val;
#pragma unroll
    for (int o = 16; o; o >>= 1) m = fmaxf(m, __shfl_xor_sync(0xffffffffu, m, o));
    if ((j & 31) == 0) red[j >> 5] = m;
    __syncthreads();
    float M = fmaxf(fmaxf(fmaxf(red[0], red[1]), fmaxf(red[2], red[3])), fmaxf(red[4], red[5]));
    __syncthreads();
    float e = (j <= i) ? expf(val - M) : 0.f;
    float s = e;
#pragma unroll
    for (int o = 16; o; o >>= 1) s += __shfl_xor_sync(0xffffffffu, s, o);
    if ((j & 31) == 0) red[j >> 5] = s;
    __syncthreads();
    float S = red[0] + red[1] + red[2] + red[3] + red[4] + red[5];
    out[((size_t)b * 192 + i) * 192 + j] = (j <= i) ? (e / S) : -1000.0f;
}

// ---------------------------------------------------------------------------
extern "C" void kernel_launch(void* const* d_in, const int* in_sizes, int n_in,
                              void* d_out, int out_size) {
    const float* E  = (const float*)d_in[0];
    const float* W1 = (const float*)d_in[1];
    const float* b1 = (const float*)d_in[2];
    const float* W2 = (const float*)d_in[3];
    const float* b2 = (const float*)d_in[4];
    const float* W3 = (const float*)d_in[5];
    const float* b3 = (const float*)d_in[6];
    float* out = (float*)d_out;

    cudaFuncSetAttribute(k1_mma, cudaFuncAttributeMaxDynamicSharedMemorySize, K1_SMEM);
    cudaFuncSetAttribute(k2_mma, cudaFuncAttributeMaxDynamicSharedMemorySize, K2_SMEM);

    kprep_e<<<(1536 * EPITCH + 255) / 256, 256>>>(E);
    kprep_w<<<(WAB_N + W1CP_N + W2_W + 255) / 256, 256>>>(W1, W2);
    k1_mma<<<48, 256, K1_SMEM>>>(b1);
    k2_mma<<<dim3(208, 8), 192, K2_SMEM>>>(b2, W3);
    k3_softmax<<<dim3(192, 8), 192>>>(out, b3);
}